// round 5
// baseline (speedup 1.0000x reference)
#include <cuda_runtime.h>
#include <cuda_fp16.h>
#include <cstdint>

// ===========================================================================
// VQPatchEncoder — single-term fp16 mma.sync GEMM + DELTA-certified exact
// argmax (fp32 rescore of near-tie rows).
// R5: K=192 (no hi/lo split, 3x fewer FLOPs), DELTA=4e-3 certification,
// 256 threads x 2 CTAs/SM, 64x32 warp tiles, 3-stage cp.async pipeline.
// ===========================================================================

#define BATCH 1024
#define NP    64
#define PD    192
#define KC    4096
#define ED    2048
#define VD    2048
#define MROWS (BATCH * NP)      // 65536
#define BM    128
#define BN    128
#define KCH   64                 // k per chunk
#define NCHUNK (PD / KCH)        // 3
#define NTILE  (KC / BN)         // 32
#define TOTIT  (NTILE * NCHUNK)  // 96
#define KGRAN  (PD / 8)          // 24 granules per A row
#define AROWB  (PD * 2)          // 384 B per A smem row
#define ASMEM  (BM * AROWB)      // 49152
#define BBUF   (KCH * BN * 2)    // 16384 per buffer
#define NBUF   3
#define GEMM_SMEM (ASMEM + NBUF * BBUF)   // 98304
#define GEMM_THREADS 256
#define DELTA 4e-3f

// ---- device-global scratch ------------------------------------------------
__device__ __half g_a [(size_t)MROWS * PD];     // fp16 patches (25 MB)
__device__ __half g_bT[(size_t)PD * KC];        // fp16 codebook^T [k][n]
__device__ float  g_patches[(size_t)MROWS * PD];
__device__ int    g_indices[MROWS];
__device__ int    g_flagged[MROWS];
__device__ int    g_nflag;

__device__ __forceinline__ uint32_t smem_u32(const void* p) {
    uint32_t a;
    asm("{ .reg .u64 t; cvta.to.shared.u64 t, %1; cvt.u32.u64 %0, t; }"
        : "=r"(a) : "l"(p));
    return a;
}
__device__ __forceinline__ void cp16(uint32_t dst, const void* src) {
    asm volatile("cp.async.cg.shared.global [%0], [%1], 16;"
                 :: "r"(dst), "l"(src) : "memory");
}
#define CP_COMMIT() asm volatile("cp.async.commit_group;" ::: "memory")
#define CP_WAIT(n)  asm volatile("cp.async.wait_group %0;" :: "n"(n) : "memory")

__device__ __forceinline__ void ldsm4(uint32_t* r, uint32_t addr) {
    asm volatile("ldmatrix.sync.aligned.m8n8.x4.shared.b16 {%0,%1,%2,%3}, [%4];"
                 : "=r"(r[0]), "=r"(r[1]), "=r"(r[2]), "=r"(r[3]) : "r"(addr));
}
__device__ __forceinline__ void ldsm4t(uint32_t* r, uint32_t addr) {
    asm volatile("ldmatrix.sync.aligned.m8n8.x4.trans.shared.b16 {%0,%1,%2,%3}, [%4];"
                 : "=r"(r[0]), "=r"(r[1]), "=r"(r[2]), "=r"(r[3]) : "r"(addr));
}
__device__ __forceinline__ void mma16816(float* c, const uint32_t* a,
                                         uint32_t b0, uint32_t b1) {
    asm volatile(
        "mma.sync.aligned.m16n8k16.row.col.f32.f16.f16.f32 "
        "{%0,%1,%2,%3}, {%4,%5,%6,%7}, {%8,%9}, {%0,%1,%2,%3};"
        : "+f"(c[0]), "+f"(c[1]), "+f"(c[2]), "+f"(c[3])
        : "r"(a[0]), "r"(a[1]), "r"(a[2]), "r"(a[3]), "r"(b0), "r"(b1));
}

// ===========================================================================
// 1) Patchify: fp32 copy (for rescore) + fp16 row for the GEMM.
// ===========================================================================
__global__ void patchify_split_kernel(const float* __restrict__ pixels) {
    int idx = blockIdx.x * blockDim.x + threadIdx.x;
    if (idx >= MROWS * PD) return;
    int d = idx % PD;
    int m = idx / PD;
    int p = m % NP, b = m / NP;
    int ch = d >> 6;
    int rem = d & 63;
    int pr = rem >> 3, pc = rem & 7;
    int r = p >> 3, c = p & 7;
    float v = pixels[(((size_t)b * 3 + ch) * 64 + (r * 8 + pr)) * 64 + (c * 8 + pc)];
    g_patches[idx] = v;
    g_a[idx] = __float2half_rn(v);
}

// ===========================================================================
// 2) Codebook -> fp16 transposed [k][n].
// ===========================================================================
__global__ void split_codebook_kernel(const float* __restrict__ cb) {
    int idx = blockIdx.x * blockDim.x + threadIdx.x;
    if (idx >= PD * KC) return;
    int n = idx % KC;
    int d = idx / KC;
    g_bT[idx] = __float2half_rn(cb[(size_t)n * PD + d]);
}

__global__ void zero_flag_kernel() { g_nflag = 0; }

// ===========================================================================
// 3) fp16 mma.sync GEMM + fused top-2 argmax.
//    512 blocks x 256 threads, 2 CTAs/SM. 8 warps: wm in {0,1} (64 M rows),
//    wn in 0..3 (32 N cols). A tile (128x192) smem-resident; B streamed in
//    64x128 chunks, 3-buffer cp.async pipeline, 1 barrier per chunk.
// ===========================================================================
__global__ __launch_bounds__(GEMM_THREADS, 2) void gemm_mma_kernel(float* __restrict__ outI) {
    extern __shared__ char smem[];
    const uint32_t sA = smem_u32(smem);
    const uint32_t sB = sA + ASMEM;
    const int tid = threadIdx.x;
    const int wid = tid >> 5;
    const int lane = tid & 31;
    const int wm = wid >> 2;    // 0..1  (M strip of 64)
    const int wn = wid & 3;     // 0..3  (N strip of 32)
    const int m0 = blockIdx.x * BM;

    // ---- A tile -> smem (group 0): 3072 granules ----
    {
        const __half* gA = g_a + (size_t)m0 * PD;
        for (int i = tid; i < BM * KGRAN; i += GEMM_THREADS) {
            int r = i / KGRAN, g = i % KGRAN;
            cp16(sA + r * AROWB + ((g ^ (r & 7)) * 16), gA + (size_t)r * PD + g * 8);
        }
        CP_COMMIT();
    }
    // ---- B chunks 0,1 of tile 0 (groups 1,2) ----
#pragma unroll
    for (int pre = 0; pre < 2; pre++) {
        const __half* src = g_bT + (size_t)(pre * KCH) * KC;
        uint32_t dst = sB + pre * BBUF;
        for (int i = tid; i < KCH * (BN / 8); i += GEMM_THREADS) {
            int r = i >> 4, g = i & 15;
            cp16(dst + r * (BN * 2) + ((g ^ (r & 7)) * 16), src + (size_t)r * KC + g * 8);
        }
        CP_COMMIT();
    }

    float acc[4][2][2][4];
#pragma unroll
    for (int a = 0; a < 4; a++)
#pragma unroll
        for (int b = 0; b < 2; b++)
#pragma unroll
            for (int c = 0; c < 2; c++)
#pragma unroll
                for (int d = 0; d < 4; d++) acc[a][b][c][d] = 0.0f;

    float b1[8], b2[8];
    int   i1[8];
#pragma unroll
    for (int s = 0; s < 8; s++) { b1[s] = -3.0e38f; b2[s] = -3.0e38f; i1[s] = 0; }

    for (int it = 0; it < TOTIT; ++it) {
        const int kc = it % NCHUNK;
        CP_WAIT(1);
        __syncthreads();

        // ---- compute chunk it from buf[it % 3] ----
        const uint32_t bbuf = sB + (it % NBUF) * BBUF;
#pragma unroll
        for (int kk = 0; kk < 4; kk++) {
            uint32_t afr[4][4];
#pragma unroll
            for (int mm = 0; mm < 4; mm++) {
                int r = wm * 64 + mm * 16 + (lane & 15);
                int g = kc * 8 + kk * 2 + (lane >> 4);
                ldsm4(afr[mm], sA + r * AROWB + ((g ^ (r & 7)) * 16));
            }
#pragma unroll
            for (int nn2 = 0; nn2 < 2; nn2++) {
                int krow = kk * 16 + (lane & 7) + ((lane & 16) ? 8 : 0);
                int g = wn * 4 + nn2 * 2 + ((lane >> 3) & 1);
                uint32_t bfr[4];
                ldsm4t(bfr, bbuf + krow * (BN * 2) + ((g ^ (krow & 7)) * 16));
#pragma unroll
                for (int mm = 0; mm < 4; mm++) {
                    mma16816(acc[mm][nn2][0], afr[mm], bfr[0], bfr[2]);
                    mma16816(acc[mm][nn2][1], afr[mm], bfr[1], bfr[3]);
                }
            }
        }

        // ---- end of N-tile: fold accumulators into running top-2 ----
        if (kc == NCHUNK - 1) {
            const int colb = (it / NCHUNK) * BN + wn * 32 + 2 * (lane & 3);
#pragma unroll
            for (int s = 0; s < 8; s++) {
                const int mm = s >> 1, h = s & 1;
#pragma unroll
                for (int nn2 = 0; nn2 < 2; nn2++) {
#pragma unroll
                    for (int hn = 0; hn < 2; hn++) {
                        int cb = colb + nn2 * 16 + hn * 8;
                        float v0 = acc[mm][nn2][hn][h * 2];
                        if (v0 > b1[s]) { b2[s] = b1[s]; b1[s] = v0; i1[s] = cb; }
                        else if (v0 > b2[s]) b2[s] = v0;
                        float v1 = acc[mm][nn2][hn][h * 2 + 1];
                        if (v1 > b1[s]) { b2[s] = b1[s]; b1[s] = v1; i1[s] = cb + 1; }
                        else if (v1 > b2[s]) b2[s] = v1;
                        acc[mm][nn2][hn][h * 2] = 0.0f;
                        acc[mm][nn2][hn][h * 2 + 1] = 0.0f;
                    }
                }
            }
        }

        // ---- prefetch chunk it+2 into buf[(it+2)%3] (freed by the barrier) ----
        if (it + 2 < TOTIT) {
            int t2 = (it + 2) / NCHUNK, k2 = (it + 2) % NCHUNK;
            const __half* src = g_bT + (size_t)(k2 * KCH) * KC + t2 * BN;
            uint32_t dst = sB + ((it + 2) % NBUF) * BBUF;
            for (int i = tid; i < KCH * (BN / 8); i += GEMM_THREADS) {
                int r = i >> 4, g = i & 15;
                cp16(dst + r * (BN * 2) + ((g ^ (r & 7)) * 16), src + (size_t)r * KC + g * 8);
            }
            CP_COMMIT();
        }
    }

    // ---- quad-lane merge (lanes sharing rows differ in lane&3) ----
#pragma unroll
    for (int s = 0; s < 8; s++) {
#pragma unroll
        for (int ofs = 1; ofs <= 2; ofs <<= 1) {
            float w1 = __shfl_xor_sync(0xFFFFFFFFu, b1[s], ofs);
            float w2 = __shfl_xor_sync(0xFFFFFFFFu, b2[s], ofs);
            int   k1 = __shfl_xor_sync(0xFFFFFFFFu, i1[s], ofs);
            if (w1 > b1[s] || (w1 == b1[s] && k1 < i1[s])) {
                b2[s] = fmaxf(b1[s], w2); b1[s] = w1; i1[s] = k1;
            } else {
                b2[s] = fmaxf(b2[s], w1);
            }
        }
    }

    // ---- cross-warp reduction via smem (reuse B buffers) ----
    __syncthreads();
    float* rv1 = (float*)(smem + ASMEM);
    float* rv2 = rv1 + BM * 4;
    int*   ri1 = (int*)(rv2 + BM * 4);
    if ((lane & 3) == 0) {
#pragma unroll
        for (int s = 0; s < 8; s++) {
            int row = wm * 64 + (s >> 1) * 16 + (s & 1) * 8 + (lane >> 2);
            rv1[row * 4 + wn] = b1[s];
            rv2[row * 4 + wn] = b2[s];
            ri1[row * 4 + wn] = i1[s];
        }
    }
    __syncthreads();
    if (tid < BM) {
        float v1 = rv1[tid * 4], v2 = rv2[tid * 4];
        int   j1 = ri1[tid * 4];
#pragma unroll
        for (int t = 1; t < 4; t++) {
            float w1 = rv1[tid * 4 + t], w2 = rv2[tid * 4 + t];
            int   k1 = ri1[tid * 4 + t];
            if (w1 > v1 || (w1 == v1 && k1 < j1)) { v2 = fmaxf(v1, w2); v1 = w1; j1 = k1; }
            else v2 = fmaxf(v2, w1);
        }
        int row = m0 + tid;
        g_indices[row] = j1;
        outI[row] = (float)j1;
        if (v1 - v2 < DELTA) {
            int s = atomicAdd(&g_nflag, 1);
            g_flagged[s] = row;
        }
    }
}

// ===========================================================================
// 4) Exact fp32 rescore for near-tie rows (sequential-d accumulation,
//    first-occurrence tie-break) — bit-exact vs reference argmax.
// ===========================================================================
__global__ __launch_bounds__(256) void rescore_kernel(const float* __restrict__ cb,
                                                      float* __restrict__ outI) {
    __shared__ float sp[PD];
    __shared__ float sv[256];
    __shared__ int si[256];
    const int nf = g_nflag;
    for (int f = blockIdx.x; f < nf; f += gridDim.x) {
        const int m = g_flagged[f];
        for (int d = threadIdx.x; d < PD; d += 256) sp[d] = g_patches[(size_t)m * PD + d];
        __syncthreads();
        float bv = -3.0e38f;
        int bi = 0;
        for (int k = threadIdx.x; k < KC; k += 256) {
            const float* crow = cb + (size_t)k * PD;
            float s = 0.0f;
#pragma unroll 8
            for (int d = 0; d < PD; d++) s = fmaf(sp[d], crow[d], s);
            if (s > bv) { bv = s; bi = k; }
        }
        sv[threadIdx.x] = bv;
        si[threadIdx.x] = bi;
        __syncthreads();
        if (threadIdx.x == 0) {
            float v = sv[0]; int ix = si[0];
            for (int t = 1; t < 256; t++)
                if (sv[t] > v || (sv[t] == v && si[t] < ix)) { v = sv[t]; ix = si[t]; }
            g_indices[m] = ix;
            outI[m] = (float)ix;
        }
        __syncthreads();
    }
}

// ===========================================================================
// 5) Embedding means (global + agent 3x3). 2 blocks per image.
// ===========================================================================
__global__ __launch_bounds__(256) void embed_mean_kernel(
    const float* __restrict__ emb, float* __restrict__ outR, float* __restrict__ outL)
{
    const int b = blockIdx.x;
    const int e0 = blockIdx.y * (ED / 2);
    __shared__ int sIdx[NP];
    if (threadIdx.x < NP) sIdx[threadIdx.x] = g_indices[b * NP + threadIdx.x];
    __syncthreads();
    for (int e = e0 + threadIdx.x; e < e0 + ED / 2; e += 256) {
        float s = 0.0f, sl = 0.0f;
#pragma unroll 8
        for (int p = 0; p < NP; p++) {
            float v = emb[(size_t)sIdx[p] * ED + e];
            s += v;
            int r = p >> 3, c = p & 7;
            if (r >= 3 && r < 6 && c >= 3 && c < 6) sl += v;
        }
        outR[(size_t)b * ED + e] = s * (1.0f / 64.0f);
        outL[(size_t)b * ED + e] = sl * (1.0f / 9.0f);
    }
}

// ===========================================================================
// 6) VSA over 16 central patches. 2 blocks per image.
// ===========================================================================
__global__ __launch_bounds__(256) void vsa_kernel(
    const float* __restrict__ cbv, const float* __restrict__ roles,
    float* __restrict__ outV)
{
    const int b = blockIdx.x;
    const int v0 = blockIdx.y * (VD / 2);
    __shared__ int sIdx[16];
    __shared__ int sPos[16];
    if (threadIdx.x < 16) {
        int r = 2 + (threadIdx.x >> 2);
        int c = 2 + (threadIdx.x & 3);
        int p = r * 8 + c;
        sPos[threadIdx.x] = p;
        sIdx[threadIdx.x] = g_indices[b * NP + p];
    }
    __syncthreads();
    for (int v = v0 + threadIdx.x; v < v0 + VD / 2; v += 256) {
        int cnt = 0;
#pragma unroll
        for (int t = 0; t < 16; t++) {
            float a = cbv[(size_t)sIdx[t] * VD + v];
            float q = roles[(size_t)sPos[t] * VD + v];
            cnt += (a != q);
        }
        outV[(size_t)b * VD + v] = (cnt > 8) ? 1.0f : 0.0f;
    }
}

// ===========================================================================
extern "C" void kernel_launch(void* const* d_in, const int* in_sizes, int n_in,
                              void* d_out, int out_size)
{
    const float* pixels     = (const float*)d_in[0];
    const float* codebook   = (const float*)d_in[1];
    const float* embeddings = (const float*)d_in[2];
    const float* cbv        = (const float*)d_in[3];
    const float* roles      = (const float*)d_in[4];

    float* out  = (float*)d_out;
    float* outR = out;
    float* outV = out + (size_t)BATCH * ED;
    float* outI = out + 2 * (size_t)BATCH * ED;
    float* outL = out + 2 * (size_t)BATCH * ED + (size_t)BATCH * NP;

    static bool attr_set = false;
    if (!attr_set) {
        cudaFuncSetAttribute(gemm_mma_kernel,
                             cudaFuncAttributeMaxDynamicSharedMemorySize, GEMM_SMEM);
        attr_set = true;
    }

    patchify_split_kernel<<<(MROWS * PD + 255) / 256, 256>>>(pixels);
    split_codebook_kernel<<<(PD * KC + 255) / 256, 256>>>(codebook);
    zero_flag_kernel<<<1, 1>>>();
    gemm_mma_kernel<<<MROWS / BM, GEMM_THREADS, GEMM_SMEM>>>(outI);
    rescore_kernel<<<512, 256>>>(codebook, outI);
    embed_mean_kernel<<<dim3(BATCH, 2), 256>>>(embeddings, outR, outL);
    vsa_kernel<<<dim3(BATCH, 2), 256>>>(cbv, roles, outV);
}

// round 6
// speedup vs baseline: 2.4604x; 2.4604x over previous
#include <cuda_runtime.h>
#include <cuda_fp16.h>
#include <cstdint>

// ===========================================================================
// VQPatchEncoder — single-term fp16 mma.sync GEMM + DELTA-certified exact
// argmax. R6: tiled batch rescore (fixes R5's 8x-amplified per-row codebook
// rescans), float4 embed_mean / vsa.
// ===========================================================================

#define BATCH 1024
#define NP    64
#define PD    192
#define KC    4096
#define ED    2048
#define VD    2048
#define MROWS (BATCH * NP)      // 65536
#define BM    128
#define BN    128
#define KCH   64
#define NCHUNK (PD / KCH)        // 3
#define NTILE  (KC / BN)         // 32
#define TOTIT  (NTILE * NCHUNK)  // 96
#define KGRAN  (PD / 8)          // 24
#define AROWB  (PD * 2)          // 384
#define ASMEM  (BM * AROWB)      // 49152
#define BBUF   (KCH * BN * 2)    // 16384
#define NBUF   3
#define GEMM_SMEM (ASMEM + NBUF * BBUF)   // 98304
#define GEMM_THREADS 256
#define DELTA 4e-3f

// ---- device-global scratch ------------------------------------------------
__device__ __half g_a [(size_t)MROWS * PD];
__device__ __half g_bT[(size_t)PD * KC];
__device__ float  g_patches[(size_t)MROWS * PD];
__device__ int    g_indices[MROWS];
__device__ int    g_flagged[MROWS];
__device__ int    g_nflag;
__device__ float  g_part_val[(size_t)MROWS * 4];
__device__ int    g_part_idx[(size_t)MROWS * 4];

__device__ __forceinline__ uint32_t smem_u32(const void* p) {
    uint32_t a;
    asm("{ .reg .u64 t; cvta.to.shared.u64 t, %1; cvt.u32.u64 %0, t; }"
        : "=r"(a) : "l"(p));
    return a;
}
__device__ __forceinline__ void cp16(uint32_t dst, const void* src) {
    asm volatile("cp.async.cg.shared.global [%0], [%1], 16;"
                 :: "r"(dst), "l"(src) : "memory");
}
#define CP_COMMIT() asm volatile("cp.async.commit_group;" ::: "memory")
#define CP_WAIT(n)  asm volatile("cp.async.wait_group %0;" :: "n"(n) : "memory")

__device__ __forceinline__ void ldsm4(uint32_t* r, uint32_t addr) {
    asm volatile("ldmatrix.sync.aligned.m8n8.x4.shared.b16 {%0,%1,%2,%3}, [%4];"
                 : "=r"(r[0]), "=r"(r[1]), "=r"(r[2]), "=r"(r[3]) : "r"(addr));
}
__device__ __forceinline__ void ldsm4t(uint32_t* r, uint32_t addr) {
    asm volatile("ldmatrix.sync.aligned.m8n8.x4.trans.shared.b16 {%0,%1,%2,%3}, [%4];"
                 : "=r"(r[0]), "=r"(r[1]), "=r"(r[2]), "=r"(r[3]) : "r"(addr));
}
__device__ __forceinline__ void mma16816(float* c, const uint32_t* a,
                                         uint32_t b0, uint32_t b1) {
    asm volatile(
        "mma.sync.aligned.m16n8k16.row.col.f32.f16.f16.f32 "
        "{%0,%1,%2,%3}, {%4,%5,%6,%7}, {%8,%9}, {%0,%1,%2,%3};"
        : "+f"(c[0]), "+f"(c[1]), "+f"(c[2]), "+f"(c[3])
        : "r"(a[0]), "r"(a[1]), "r"(a[2]), "r"(a[3]), "r"(b0), "r"(b1));
}

// ===========================================================================
// 1) Patchify: fp32 copy + fp16 row.
// ===========================================================================
__global__ void patchify_split_kernel(const float* __restrict__ pixels) {
    int idx = blockIdx.x * blockDim.x + threadIdx.x;
    if (idx >= MROWS * PD) return;
    int d = idx % PD;
    int m = idx / PD;
    int p = m % NP, b = m / NP;
    int ch = d >> 6;
    int rem = d & 63;
    int pr = rem >> 3, pc = rem & 7;
    int r = p >> 3, c = p & 7;
    float v = pixels[(((size_t)b * 3 + ch) * 64 + (r * 8 + pr)) * 64 + (c * 8 + pc)];
    g_patches[idx] = v;
    g_a[idx] = __float2half_rn(v);
}

// ===========================================================================
// 2) Codebook -> fp16 transposed [k][n].
// ===========================================================================
__global__ void split_codebook_kernel(const float* __restrict__ cb) {
    int idx = blockIdx.x * blockDim.x + threadIdx.x;
    if (idx >= PD * KC) return;
    int n = idx % KC;
    int d = idx / KC;
    g_bT[idx] = __float2half_rn(cb[(size_t)n * PD + d]);
}

__global__ void zero_flag_kernel() { g_nflag = 0; }

// ===========================================================================
// 3) fp16 mma.sync GEMM + fused top-2 argmax (unchanged from R5: 494us).
// ===========================================================================
__global__ __launch_bounds__(GEMM_THREADS, 2) void gemm_mma_kernel(float* __restrict__ outI) {
    extern __shared__ char smem[];
    const uint32_t sA = smem_u32(smem);
    const uint32_t sB = sA + ASMEM;
    const int tid = threadIdx.x;
    const int wid = tid >> 5;
    const int lane = tid & 31;
    const int wm = wid >> 2;
    const int wn = wid & 3;
    const int m0 = blockIdx.x * BM;

    {
        const __half* gA = g_a + (size_t)m0 * PD;
        for (int i = tid; i < BM * KGRAN; i += GEMM_THREADS) {
            int r = i / KGRAN, g = i % KGRAN;
            cp16(sA + r * AROWB + ((g ^ (r & 7)) * 16), gA + (size_t)r * PD + g * 8);
        }
        CP_COMMIT();
    }
#pragma unroll
    for (int pre = 0; pre < 2; pre++) {
        const __half* src = g_bT + (size_t)(pre * KCH) * KC;
        uint32_t dst = sB + pre * BBUF;
        for (int i = tid; i < KCH * (BN / 8); i += GEMM_THREADS) {
            int r = i >> 4, g = i & 15;
            cp16(dst + r * (BN * 2) + ((g ^ (r & 7)) * 16), src + (size_t)r * KC + g * 8);
        }
        CP_COMMIT();
    }

    float acc[4][2][2][4];
#pragma unroll
    for (int a = 0; a < 4; a++)
#pragma unroll
        for (int b = 0; b < 2; b++)
#pragma unroll
            for (int c = 0; c < 2; c++)
#pragma unroll
                for (int d = 0; d < 4; d++) acc[a][b][c][d] = 0.0f;

    float b1[8], b2[8];
    int   i1[8];
#pragma unroll
    for (int s = 0; s < 8; s++) { b1[s] = -3.0e38f; b2[s] = -3.0e38f; i1[s] = 0; }

    for (int it = 0; it < TOTIT; ++it) {
        const int kc = it % NCHUNK;
        CP_WAIT(1);
        __syncthreads();

        const uint32_t bbuf = sB + (it % NBUF) * BBUF;
#pragma unroll
        for (int kk = 0; kk < 4; kk++) {
            uint32_t afr[4][4];
#pragma unroll
            for (int mm = 0; mm < 4; mm++) {
                int r = wm * 64 + mm * 16 + (lane & 15);
                int g = kc * 8 + kk * 2 + (lane >> 4);
                ldsm4(afr[mm], sA + r * AROWB + ((g ^ (r & 7)) * 16));
            }
#pragma unroll
            for (int nn2 = 0; nn2 < 2; nn2++) {
                int krow = kk * 16 + (lane & 7) + ((lane & 16) ? 8 : 0);
                int g = wn * 4 + nn2 * 2 + ((lane >> 3) & 1);
                uint32_t bfr[4];
                ldsm4t(bfr, bbuf + krow * (BN * 2) + ((g ^ (krow & 7)) * 16));
#pragma unroll
                for (int mm = 0; mm < 4; mm++) {
                    mma16816(acc[mm][nn2][0], afr[mm], bfr[0], bfr[2]);
                    mma16816(acc[mm][nn2][1], afr[mm], bfr[1], bfr[3]);
                }
            }
        }

        if (kc == NCHUNK - 1) {
            const int colb = (it / NCHUNK) * BN + wn * 32 + 2 * (lane & 3);
#pragma unroll
            for (int s = 0; s < 8; s++) {
                const int mm = s >> 1, h = s & 1;
#pragma unroll
                for (int nn2 = 0; nn2 < 2; nn2++) {
#pragma unroll
                    for (int hn = 0; hn < 2; hn++) {
                        int cb = colb + nn2 * 16 + hn * 8;
                        float v0 = acc[mm][nn2][hn][h * 2];
                        if (v0 > b1[s]) { b2[s] = b1[s]; b1[s] = v0; i1[s] = cb; }
                        else if (v0 > b2[s]) b2[s] = v0;
                        float v1 = acc[mm][nn2][hn][h * 2 + 1];
                        if (v1 > b1[s]) { b2[s] = b1[s]; b1[s] = v1; i1[s] = cb + 1; }
                        else if (v1 > b2[s]) b2[s] = v1;
                        acc[mm][nn2][hn][h * 2] = 0.0f;
                        acc[mm][nn2][hn][h * 2 + 1] = 0.0f;
                    }
                }
            }
        }

        if (it + 2 < TOTIT) {
            int t2 = (it + 2) / NCHUNK, k2 = (it + 2) % NCHUNK;
            const __half* src = g_bT + (size_t)(k2 * KCH) * KC + t2 * BN;
            uint32_t dst = sB + ((it + 2) % NBUF) * BBUF;
            for (int i = tid; i < KCH * (BN / 8); i += GEMM_THREADS) {
                int r = i >> 4, g = i & 15;
                cp16(dst + r * (BN * 2) + ((g ^ (r & 7)) * 16), src + (size_t)r * KC + g * 8);
            }
            CP_COMMIT();
        }
    }

#pragma unroll
    for (int s = 0; s < 8; s++) {
#pragma unroll
        for (int ofs = 1; ofs <= 2; ofs <<= 1) {
            float w1 = __shfl_xor_sync(0xFFFFFFFFu, b1[s], ofs);
            float w2 = __shfl_xor_sync(0xFFFFFFFFu, b2[s], ofs);
            int   k1 = __shfl_xor_sync(0xFFFFFFFFu, i1[s], ofs);
            if (w1 > b1[s] || (w1 == b1[s] && k1 < i1[s])) {
                b2[s] = fmaxf(b1[s], w2); b1[s] = w1; i1[s] = k1;
            } else {
                b2[s] = fmaxf(b2[s], w1);
            }
        }
    }

    __syncthreads();
    float* rv1 = (float*)(smem + ASMEM);
    float* rv2 = rv1 + BM * 4;
    int*   ri1 = (int*)(rv2 + BM * 4);
    if ((lane & 3) == 0) {
#pragma unroll
        for (int s = 0; s < 8; s++) {
            int row = wm * 64 + (s >> 1) * 16 + (s & 1) * 8 + (lane >> 2);
            rv1[row * 4 + wn] = b1[s];
            rv2[row * 4 + wn] = b2[s];
            ri1[row * 4 + wn] = i1[s];
        }
    }
    __syncthreads();
    if (tid < BM) {
        float v1 = rv1[tid * 4], v2 = rv2[tid * 4];
        int   j1 = ri1[tid * 4];
#pragma unroll
        for (int t = 1; t < 4; t++) {
            float w1 = rv1[tid * 4 + t], w2 = rv2[tid * 4 + t];
            int   k1 = ri1[tid * 4 + t];
            if (w1 > v1 || (w1 == v1 && k1 < j1)) { v2 = fmaxf(v1, w2); v1 = w1; j1 = k1; }
            else v2 = fmaxf(v2, w1);
        }
        int row = m0 + tid;
        g_indices[row] = j1;
        outI[row] = (float)j1;
        if (v1 - v2 < DELTA) {
            int s = atomicAdd(&g_nflag, 1);
            g_flagged[s] = row;
        }
    }
}

// ===========================================================================
// 4a) Tiled batch rescore. Work item = (group of 16 flagged rows) x
//     (1024-code slice). 256 threads = 16 rows x 16 code-lanes; 16 threads
//     share each codebook row (broadcast float4 loads). Per-thread codes
//     ascending -> strict '>' keeps first occurrence within slice.
// ===========================================================================
__global__ __launch_bounds__(256) void rescore_part_kernel(const float* __restrict__ cb) {
    __shared__ float4 sp[16][48];     // 16 rows x 192 f32
    __shared__ float  rv[16][16];
    __shared__ int    ri[16][16];
    const int nf = g_nflag;
    if (nf == 0) return;
    const int ngroups = (nf + 15) >> 4;
    const int nitems = ngroups * 4;
    const int tid = threadIdx.x;
    const int r = tid & 15;       // row within group
    const int cl = tid >> 4;      // code lane

    for (int item = blockIdx.x; item < nitems; item += gridDim.x) {
        const int g = item >> 2;
        const int s = item & 3;
        __syncthreads();
        // load 16 patch rows (dup last row for padding)
        for (int i = tid; i < 16 * 48; i += 256) {
            int rr = i / 48, qq = i % 48;
            int f = g * 16 + rr;
            int m = g_flagged[(f < nf) ? f : (nf - 1)];
            sp[rr][qq] = ((const float4*)(g_patches + (size_t)m * PD))[qq];
        }
        __syncthreads();

        float bv = -3.0e38f;
        int bi = 0;
        const int kbase = s * 1024 + cl * 64;
        for (int j = 0; j < 64; j++) {
            const int k = kbase + j;
            const float4* crow = (const float4*)(cb + (size_t)k * PD);
            float acc = 0.0f;
#pragma unroll 12
            for (int q = 0; q < 48; q++) {
                float4 c4 = crow[q];
                float4 p4 = sp[r][q];
                acc = fmaf(p4.x, c4.x, acc);
                acc = fmaf(p4.y, c4.y, acc);
                acc = fmaf(p4.z, c4.z, acc);
                acc = fmaf(p4.w, c4.w, acc);
            }
            if (acc > bv) { bv = acc; bi = k; }
        }
        rv[r][cl] = bv;
        ri[r][cl] = bi;
        __syncthreads();
        if (tid < 16) {
            float v = rv[tid][0];
            int ix = ri[tid][0];
#pragma unroll
            for (int t = 1; t < 16; t++) {
                float w = rv[tid][t];
                int k1 = ri[tid][t];
                if (w > v || (w == v && k1 < ix)) { v = w; ix = k1; }
            }
            int f = g * 16 + tid;
            if (f < nf) {
                g_part_val[(size_t)f * 4 + s] = v;
                g_part_idx[(size_t)f * 4 + s] = ix;
            }
        }
    }
}

// 4b) Combine slices (ascending s -> lowest-index tiebreak globally).
__global__ void rescore_combine_kernel(float* __restrict__ outI) {
    int f = blockIdx.x * blockDim.x + threadIdx.x;
    if (f >= g_nflag) return;
    float bv = g_part_val[(size_t)f * 4];
    int bi = g_part_idx[(size_t)f * 4];
#pragma unroll
    for (int s = 1; s < 4; s++) {
        float v = g_part_val[(size_t)f * 4 + s];
        int ix = g_part_idx[(size_t)f * 4 + s];
        if (v > bv || (v == bv && ix < bi)) { bv = v; bi = ix; }
    }
    int m = g_flagged[f];
    g_indices[m] = bi;
    outI[m] = (float)bi;
}

// ===========================================================================
// 5) Embedding means, float4. grid (BATCH, 2), 256 threads: one float4 each.
// ===========================================================================
__global__ __launch_bounds__(256) void embed_mean_kernel(
    const float* __restrict__ emb, float* __restrict__ outR, float* __restrict__ outL)
{
    const int b = blockIdx.x;
    __shared__ int sIdx[NP];
    if (threadIdx.x < NP) sIdx[threadIdx.x] = g_indices[b * NP + threadIdx.x];
    __syncthreads();
    const int e4 = blockIdx.y * 256 + threadIdx.x;   // float4 index in [0,512)
    const float4* emb4 = (const float4*)emb;
    float4 s = make_float4(0.f, 0.f, 0.f, 0.f);
    float4 sl = make_float4(0.f, 0.f, 0.f, 0.f);
#pragma unroll 8
    for (int p = 0; p < NP; p++) {
        float4 v = emb4[(size_t)sIdx[p] * (ED / 4) + e4];
        s.x += v.x; s.y += v.y; s.z += v.z; s.w += v.w;
        int r = p >> 3, c = p & 7;
        if (r >= 3 && r < 6 && c >= 3 && c < 6) {
            sl.x += v.x; sl.y += v.y; sl.z += v.z; sl.w += v.w;
        }
    }
    const float iR = 1.0f / 64.0f, iL = 1.0f / 9.0f;
    ((float4*)outR)[(size_t)b * (ED / 4) + e4] =
        make_float4(s.x * iR, s.y * iR, s.z * iR, s.w * iR);
    ((float4*)outL)[(size_t)b * (ED / 4) + e4] =
        make_float4(sl.x * iL, sl.y * iL, sl.z * iL, sl.w * iL);
}

// ===========================================================================
// 6) VSA, float4. grid (BATCH, 2), 256 threads: one float4 each.
// ===========================================================================
__global__ __launch_bounds__(256) void vsa_kernel(
    const float* __restrict__ cbv, const float* __restrict__ roles,
    float* __restrict__ outV)
{
    const int b = blockIdx.x;
    __shared__ int sIdx[16];
    __shared__ int sPos[16];
    if (threadIdx.x < 16) {
        int r = 2 + (threadIdx.x >> 2);
        int c = 2 + (threadIdx.x & 3);
        int p = r * 8 + c;
        sPos[threadIdx.x] = p;
        sIdx[threadIdx.x] = g_indices[b * NP + p];
    }
    __syncthreads();
    const int v4 = blockIdx.y * 256 + threadIdx.x;   // float4 index in [0,512)
    const float4* cbv4 = (const float4*)cbv;
    const float4* rol4 = (const float4*)roles;
    int cx = 0, cy = 0, cz = 0, cw = 0;
#pragma unroll
    for (int t = 0; t < 16; t++) {
        float4 a = cbv4[(size_t)sIdx[t] * (VD / 4) + v4];
        float4 q = rol4[(size_t)sPos[t] * (VD / 4) + v4];
        cx += (a.x != q.x); cy += (a.y != q.y);
        cz += (a.z != q.z); cw += (a.w != q.w);
    }
    ((float4*)outV)[(size_t)b * (VD / 4) + v4] =
        make_float4(cx > 8 ? 1.f : 0.f, cy > 8 ? 1.f : 0.f,
                    cz > 8 ? 1.f : 0.f, cw > 8 ? 1.f : 0.f);
}

// ===========================================================================
extern "C" void kernel_launch(void* const* d_in, const int* in_sizes, int n_in,
                              void* d_out, int out_size)
{
    const float* pixels     = (const float*)d_in[0];
    const float* codebook   = (const float*)d_in[1];
    const float* embeddings = (const float*)d_in[2];
    const float* cbv        = (const float*)d_in[3];
    const float* roles      = (const float*)d_in[4];

    float* out  = (float*)d_out;
    float* outR = out;
    float* outV = out + (size_t)BATCH * ED;
    float* outI = out + 2 * (size_t)BATCH * ED;
    float* outL = out + 2 * (size_t)BATCH * ED + (size_t)BATCH * NP;

    static bool attr_set = false;
    if (!attr_set) {
        cudaFuncSetAttribute(gemm_mma_kernel,
                             cudaFuncAttributeMaxDynamicSharedMemorySize, GEMM_SMEM);
        attr_set = true;
    }

    patchify_split_kernel<<<(MROWS * PD + 255) / 256, 256>>>(pixels);
    split_codebook_kernel<<<(PD * KC + 255) / 256, 256>>>(codebook);
    zero_flag_kernel<<<1, 1>>>();
    gemm_mma_kernel<<<MROWS / BM, GEMM_THREADS, GEMM_SMEM>>>(outI);
    rescore_part_kernel<<<2048, 256>>>(codebook);
    rescore_combine_kernel<<<MROWS / 256, 256>>>(outI);
    embed_mean_kernel<<<dim3(BATCH, 2), 256>>>(embeddings, outR, outL);
    vsa_kernel<<<dim3(BATCH, 2), 256>>>(cbv, roles, outV);
}

// round 7
// speedup vs baseline: 5.3624x; 2.1795x over previous
#include <cuda_runtime.h>
#include <cuda_fp16.h>
#include <cstdint>

// ===========================================================================
// VQPatchEncoder — single-term fp16 mma.sync GEMM + DELTA-certified exact
// argmax. R7: rescore smem tile transposed+padded (kills the 16-way bank
// conflict that cost ~900us in R6). GEMM unchanged (495us, next target).
// ===========================================================================

#define BATCH 1024
#define NP    64
#define PD    192
#define KC    4096
#define ED    2048
#define VD    2048
#define MROWS (BATCH * NP)      // 65536
#define BM    128
#define BN    128
#define KCH   64
#define NCHUNK (PD / KCH)        // 3
#define NTILE  (KC / BN)         // 32
#define TOTIT  (NTILE * NCHUNK)  // 96
#define KGRAN  (PD / 8)          // 24
#define AROWB  (PD * 2)          // 384
#define ASMEM  (BM * AROWB)      // 49152
#define BBUF   (KCH * BN * 2)    // 16384
#define NBUF   3
#define GEMM_SMEM (ASMEM + NBUF * BBUF)   // 98304
#define GEMM_THREADS 256
#define DELTA 4e-3f

// ---- device-global scratch ------------------------------------------------
__device__ __half g_a [(size_t)MROWS * PD];
__device__ __half g_bT[(size_t)PD * KC];
__device__ float  g_patches[(size_t)MROWS * PD];
__device__ int    g_indices[MROWS];
__device__ int    g_flagged[MROWS];
__device__ int    g_nflag;
__device__ float  g_part_val[(size_t)MROWS * 4];
__device__ int    g_part_idx[(size_t)MROWS * 4];

__device__ __forceinline__ uint32_t smem_u32(const void* p) {
    uint32_t a;
    asm("{ .reg .u64 t; cvta.to.shared.u64 t, %1; cvt.u32.u64 %0, t; }"
        : "=r"(a) : "l"(p));
    return a;
}
__device__ __forceinline__ void cp16(uint32_t dst, const void* src) {
    asm volatile("cp.async.cg.shared.global [%0], [%1], 16;"
                 :: "r"(dst), "l"(src) : "memory");
}
#define CP_COMMIT() asm volatile("cp.async.commit_group;" ::: "memory")
#define CP_WAIT(n)  asm volatile("cp.async.wait_group %0;" :: "n"(n) : "memory")

__device__ __forceinline__ void ldsm4(uint32_t* r, uint32_t addr) {
    asm volatile("ldmatrix.sync.aligned.m8n8.x4.shared.b16 {%0,%1,%2,%3}, [%4];"
                 : "=r"(r[0]), "=r"(r[1]), "=r"(r[2]), "=r"(r[3]) : "r"(addr));
}
__device__ __forceinline__ void ldsm4t(uint32_t* r, uint32_t addr) {
    asm volatile("ldmatrix.sync.aligned.m8n8.x4.trans.shared.b16 {%0,%1,%2,%3}, [%4];"
                 : "=r"(r[0]), "=r"(r[1]), "=r"(r[2]), "=r"(r[3]) : "r"(addr));
}
__device__ __forceinline__ void mma16816(float* c, const uint32_t* a,
                                         uint32_t b0, uint32_t b1) {
    asm volatile(
        "mma.sync.aligned.m16n8k16.row.col.f32.f16.f16.f32 "
        "{%0,%1,%2,%3}, {%4,%5,%6,%7}, {%8,%9}, {%0,%1,%2,%3};"
        : "+f"(c[0]), "+f"(c[1]), "+f"(c[2]), "+f"(c[3])
        : "r"(a[0]), "r"(a[1]), "r"(a[2]), "r"(a[3]), "r"(b0), "r"(b1));
}

// ===========================================================================
// 1) Patchify: fp32 copy + fp16 row.
// ===========================================================================
__global__ void patchify_split_kernel(const float* __restrict__ pixels) {
    int idx = blockIdx.x * blockDim.x + threadIdx.x;
    if (idx >= MROWS * PD) return;
    int d = idx % PD;
    int m = idx / PD;
    int p = m % NP, b = m / NP;
    int ch = d >> 6;
    int rem = d & 63;
    int pr = rem >> 3, pc = rem & 7;
    int r = p >> 3, c = p & 7;
    float v = pixels[(((size_t)b * 3 + ch) * 64 + (r * 8 + pr)) * 64 + (c * 8 + pc)];
    g_patches[idx] = v;
    g_a[idx] = __float2half_rn(v);
}

// ===========================================================================
// 2) Codebook -> fp16 transposed [k][n].
// ===========================================================================
__global__ void split_codebook_kernel(const float* __restrict__ cb) {
    int idx = blockIdx.x * blockDim.x + threadIdx.x;
    if (idx >= PD * KC) return;
    int n = idx % KC;
    int d = idx / KC;
    g_bT[idx] = __float2half_rn(cb[(size_t)n * PD + d]);
}

__global__ void zero_flag_kernel() { g_nflag = 0; }

// ===========================================================================
// 3) fp16 mma.sync GEMM + fused top-2 argmax (unchanged: 495us measured).
// ===========================================================================
__global__ __launch_bounds__(GEMM_THREADS, 2) void gemm_mma_kernel(float* __restrict__ outI) {
    extern __shared__ char smem[];
    const uint32_t sA = smem_u32(smem);
    const uint32_t sB = sA + ASMEM;
    const int tid = threadIdx.x;
    const int wid = tid >> 5;
    const int lane = tid & 31;
    const int wm = wid >> 2;
    const int wn = wid & 3;
    const int m0 = blockIdx.x * BM;

    {
        const __half* gA = g_a + (size_t)m0 * PD;
        for (int i = tid; i < BM * KGRAN; i += GEMM_THREADS) {
            int r = i / KGRAN, g = i % KGRAN;
            cp16(sA + r * AROWB + ((g ^ (r & 7)) * 16), gA + (size_t)r * PD + g * 8);
        }
        CP_COMMIT();
    }
#pragma unroll
    for (int pre = 0; pre < 2; pre++) {
        const __half* src = g_bT + (size_t)(pre * KCH) * KC;
        uint32_t dst = sB + pre * BBUF;
        for (int i = tid; i < KCH * (BN / 8); i += GEMM_THREADS) {
            int r = i >> 4, g = i & 15;
            cp16(dst + r * (BN * 2) + ((g ^ (r & 7)) * 16), src + (size_t)r * KC + g * 8);
        }
        CP_COMMIT();
    }

    float acc[4][2][2][4];
#pragma unroll
    for (int a = 0; a < 4; a++)
#pragma unroll
        for (int b = 0; b < 2; b++)
#pragma unroll
            for (int c = 0; c < 2; c++)
#pragma unroll
                for (int d = 0; d < 4; d++) acc[a][b][c][d] = 0.0f;

    float b1[8], b2[8];
    int   i1[8];
#pragma unroll
    for (int s = 0; s < 8; s++) { b1[s] = -3.0e38f; b2[s] = -3.0e38f; i1[s] = 0; }

    for (int it = 0; it < TOTIT; ++it) {
        const int kc = it % NCHUNK;
        CP_WAIT(1);
        __syncthreads();

        const uint32_t bbuf = sB + (it % NBUF) * BBUF;
#pragma unroll
        for (int kk = 0; kk < 4; kk++) {
            uint32_t afr[4][4];
#pragma unroll
            for (int mm = 0; mm < 4; mm++) {
                int r = wm * 64 + mm * 16 + (lane & 15);
                int g = kc * 8 + kk * 2 + (lane >> 4);
                ldsm4(afr[mm], sA + r * AROWB + ((g ^ (r & 7)) * 16));
            }
#pragma unroll
            for (int nn2 = 0; nn2 < 2; nn2++) {
                int krow = kk * 16 + (lane & 7) + ((lane & 16) ? 8 : 0);
                int g = wn * 4 + nn2 * 2 + ((lane >> 3) & 1);
                uint32_t bfr[4];
                ldsm4t(bfr, bbuf + krow * (BN * 2) + ((g ^ (krow & 7)) * 16));
#pragma unroll
                for (int mm = 0; mm < 4; mm++) {
                    mma16816(acc[mm][nn2][0], afr[mm], bfr[0], bfr[2]);
                    mma16816(acc[mm][nn2][1], afr[mm], bfr[1], bfr[3]);
                }
            }
        }

        if (kc == NCHUNK - 1) {
            const int colb = (it / NCHUNK) * BN + wn * 32 + 2 * (lane & 3);
#pragma unroll
            for (int s = 0; s < 8; s++) {
                const int mm = s >> 1, h = s & 1;
#pragma unroll
                for (int nn2 = 0; nn2 < 2; nn2++) {
#pragma unroll
                    for (int hn = 0; hn < 2; hn++) {
                        int cb = colb + nn2 * 16 + hn * 8;
                        float v0 = acc[mm][nn2][hn][h * 2];
                        if (v0 > b1[s]) { b2[s] = b1[s]; b1[s] = v0; i1[s] = cb; }
                        else if (v0 > b2[s]) b2[s] = v0;
                        float v1 = acc[mm][nn2][hn][h * 2 + 1];
                        if (v1 > b1[s]) { b2[s] = b1[s]; b1[s] = v1; i1[s] = cb + 1; }
                        else if (v1 > b2[s]) b2[s] = v1;
                        acc[mm][nn2][hn][h * 2] = 0.0f;
                        acc[mm][nn2][hn][h * 2 + 1] = 0.0f;
                    }
                }
            }
        }

        if (it + 2 < TOTIT) {
            int t2 = (it + 2) / NCHUNK, k2 = (it + 2) % NCHUNK;
            const __half* src = g_bT + (size_t)(k2 * KCH) * KC + t2 * BN;
            uint32_t dst = sB + ((it + 2) % NBUF) * BBUF;
            for (int i = tid; i < KCH * (BN / 8); i += GEMM_THREADS) {
                int r = i >> 4, g = i & 15;
                cp16(dst + r * (BN * 2) + ((g ^ (r & 7)) * 16), src + (size_t)r * KC + g * 8);
            }
            CP_COMMIT();
        }
    }

#pragma unroll
    for (int s = 0; s < 8; s++) {
#pragma unroll
        for (int ofs = 1; ofs <= 2; ofs <<= 1) {
            float w1 = __shfl_xor_sync(0xFFFFFFFFu, b1[s], ofs);
            float w2 = __shfl_xor_sync(0xFFFFFFFFu, b2[s], ofs);
            int   k1 = __shfl_xor_sync(0xFFFFFFFFu, i1[s], ofs);
            if (w1 > b1[s] || (w1 == b1[s] && k1 < i1[s])) {
                b2[s] = fmaxf(b1[s], w2); b1[s] = w1; i1[s] = k1;
            } else {
                b2[s] = fmaxf(b2[s], w1);
            }
        }
    }

    __syncthreads();
    float* rv1 = (float*)(smem + ASMEM);
    float* rv2 = rv1 + BM * 4;
    int*   ri1 = (int*)(rv2 + BM * 4);
    if ((lane & 3) == 0) {
#pragma unroll
        for (int s = 0; s < 8; s++) {
            int row = wm * 64 + (s >> 1) * 16 + (s & 1) * 8 + (lane >> 2);
            rv1[row * 4 + wn] = b1[s];
            rv2[row * 4 + wn] = b2[s];
            ri1[row * 4 + wn] = i1[s];
        }
    }
    __syncthreads();
    if (tid < BM) {
        float v1 = rv1[tid * 4], v2 = rv2[tid * 4];
        int   j1 = ri1[tid * 4];
#pragma unroll
        for (int t = 1; t < 4; t++) {
            float w1 = rv1[tid * 4 + t], w2 = rv2[tid * 4 + t];
            int   k1 = ri1[tid * 4 + t];
            if (w1 > v1 || (w1 == v1 && k1 < j1)) { v2 = fmaxf(v1, w2); v1 = w1; j1 = k1; }
            else v2 = fmaxf(v2, w1);
        }
        int row = m0 + tid;
        g_indices[row] = j1;
        outI[row] = (float)j1;
        if (v1 - v2 < DELTA) {
            int s = atomicAdd(&g_nflag, 1);
            g_flagged[s] = row;
        }
    }
}

// ===========================================================================
// 4a) Tiled batch rescore, bank-conflict-free.
//     sp layout [q][r] with row stride 20 float4 (80 words): the 16 lanes
//     (r=0..15) at fixed q read 16 distinct float4s spread over all 32
//     banks -> 2 transactions (physical floor), vs 16-way conflict in R6.
//     Same sequential fp32 dot order, same first-occurrence tie-break.
// ===========================================================================
__global__ __launch_bounds__(256) void rescore_part_kernel(const float* __restrict__ cb) {
    __shared__ float4 sp[48][20];     // [q][r], r<16 used, padded
    __shared__ float  rv[16][16];
    __shared__ int    ri[16][16];
    const int nf = g_nflag;
    if (nf == 0) return;
    const int ngroups = (nf + 15) >> 4;
    const int nitems = ngroups * 4;
    const int tid = threadIdx.x;
    const int r = tid & 15;       // row within group
    const int cl = tid >> 4;      // code lane

    for (int item = blockIdx.x; item < nitems; item += gridDim.x) {
        const int g = item >> 2;
        const int s = item & 3;
        __syncthreads();
        for (int i = tid; i < 16 * 48; i += 256) {
            int rr = i / 48, qq = i % 48;
            int f = g * 16 + rr;
            int m = g_flagged[(f < nf) ? f : (nf - 1)];
            sp[qq][rr] = ((const float4*)(g_patches + (size_t)m * PD))[qq];
        }
        __syncthreads();

        float bv = -3.0e38f;
        int bi = 0;
        const int kbase = s * 1024 + cl * 64;
        for (int j = 0; j < 64; j++) {
            const int k = kbase + j;
            const float4* crow = (const float4*)(cb + (size_t)k * PD);
            float acc = 0.0f;
#pragma unroll 12
            for (int q = 0; q < 48; q++) {
                float4 c4 = crow[q];
                float4 p4 = sp[q][r];
                acc = fmaf(p4.x, c4.x, acc);
                acc = fmaf(p4.y, c4.y, acc);
                acc = fmaf(p4.z, c4.z, acc);
                acc = fmaf(p4.w, c4.w, acc);
            }
            if (acc > bv) { bv = acc; bi = k; }
        }
        rv[r][cl] = bv;
        ri[r][cl] = bi;
        __syncthreads();
        if (tid < 16) {
            float v = rv[tid][0];
            int ix = ri[tid][0];
#pragma unroll
            for (int t = 1; t < 16; t++) {
                float w = rv[tid][t];
                int k1 = ri[tid][t];
                if (w > v || (w == v && k1 < ix)) { v = w; ix = k1; }
            }
            int f = g * 16 + tid;
            if (f < nf) {
                g_part_val[(size_t)f * 4 + s] = v;
                g_part_idx[(size_t)f * 4 + s] = ix;
            }
        }
    }
}

// 4b) Combine slices (ascending s -> lowest-index tiebreak globally).
__global__ void rescore_combine_kernel(float* __restrict__ outI) {
    int f = blockIdx.x * blockDim.x + threadIdx.x;
    if (f >= g_nflag) return;
    float bv = g_part_val[(size_t)f * 4];
    int bi = g_part_idx[(size_t)f * 4];
#pragma unroll
    for (int s = 1; s < 4; s++) {
        float v = g_part_val[(size_t)f * 4 + s];
        int ix = g_part_idx[(size_t)f * 4 + s];
        if (v > bv || (v == bv && ix < bi)) { bv = v; bi = ix; }
    }
    int m = g_flagged[f];
    g_indices[m] = bi;
    outI[m] = (float)bi;
}

// ===========================================================================
// 5) Embedding means, float4.
// ===========================================================================
__global__ __launch_bounds__(256) void embed_mean_kernel(
    const float* __restrict__ emb, float* __restrict__ outR, float* __restrict__ outL)
{
    const int b = blockIdx.x;
    __shared__ int sIdx[NP];
    if (threadIdx.x < NP) sIdx[threadIdx.x] = g_indices[b * NP + threadIdx.x];
    __syncthreads();
    const int e4 = blockIdx.y * 256 + threadIdx.x;
    const float4* emb4 = (const float4*)emb;
    float4 s = make_float4(0.f, 0.f, 0.f, 0.f);
    float4 sl = make_float4(0.f, 0.f, 0.f, 0.f);
#pragma unroll 8
    for (int p = 0; p < NP; p++) {
        float4 v = emb4[(size_t)sIdx[p] * (ED / 4) + e4];
        s.x += v.x; s.y += v.y; s.z += v.z; s.w += v.w;
        int r = p >> 3, c = p & 7;
        if (r >= 3 && r < 6 && c >= 3 && c < 6) {
            sl.x += v.x; sl.y += v.y; sl.z += v.z; sl.w += v.w;
        }
    }
    const float iR = 1.0f / 64.0f, iL = 1.0f / 9.0f;
    ((float4*)outR)[(size_t)b * (ED / 4) + e4] =
        make_float4(s.x * iR, s.y * iR, s.z * iR, s.w * iR);
    ((float4*)outL)[(size_t)b * (ED / 4) + e4] =
        make_float4(sl.x * iL, sl.y * iL, sl.z * iL, sl.w * iL);
}

// ===========================================================================
// 6) VSA, float4.
// ===========================================================================
__global__ __launch_bounds__(256) void vsa_kernel(
    const float* __restrict__ cbv, const float* __restrict__ roles,
    float* __restrict__ outV)
{
    const int b = blockIdx.x;
    __shared__ int sIdx[16];
    __shared__ int sPos[16];
    if (threadIdx.x < 16) {
        int r = 2 + (threadIdx.x >> 2);
        int c = 2 + (threadIdx.x & 3);
        int p = r * 8 + c;
        sPos[threadIdx.x] = p;
        sIdx[threadIdx.x] = g_indices[b * NP + p];
    }
    __syncthreads();
    const int v4 = blockIdx.y * 256 + threadIdx.x;
    const float4* cbv4 = (const float4*)cbv;
    const float4* rol4 = (const float4*)roles;
    int cx = 0, cy = 0, cz = 0, cw = 0;
#pragma unroll
    for (int t = 0; t < 16; t++) {
        float4 a = cbv4[(size_t)sIdx[t] * (VD / 4) + v4];
        float4 q = rol4[(size_t)sPos[t] * (VD / 4) + v4];
        cx += (a.x != q.x); cy += (a.y != q.y);
        cz += (a.z != q.z); cw += (a.w != q.w);
    }
    ((float4*)outV)[(size_t)b * (VD / 4) + v4] =
        make_float4(cx > 8 ? 1.f : 0.f, cy > 8 ? 1.f : 0.f,
                    cz > 8 ? 1.f : 0.f, cw > 8 ? 1.f : 0.f);
}

// ===========================================================================
extern "C" void kernel_launch(void* const* d_in, const int* in_sizes, int n_in,
                              void* d_out, int out_size)
{
    const float* pixels     = (const float*)d_in[0];
    const float* codebook   = (const float*)d_in[1];
    const float* embeddings = (const float*)d_in[2];
    const float* cbv        = (const float*)d_in[3];
    const float* roles      = (const float*)d_in[4];

    float* out  = (float*)d_out;
    float* outR = out;
    float* outV = out + (size_t)BATCH * ED;
    float* outI = out + 2 * (size_t)BATCH * ED;
    float* outL = out + 2 * (size_t)BATCH * ED + (size_t)BATCH * NP;

    static bool attr_set = false;
    if (!attr_set) {
        cudaFuncSetAttribute(gemm_mma_kernel,
                             cudaFuncAttributeMaxDynamicSharedMemorySize, GEMM_SMEM);
        attr_set = true;
    }

    patchify_split_kernel<<<(MROWS * PD + 255) / 256, 256>>>(pixels);
    split_codebook_kernel<<<(PD * KC + 255) / 256, 256>>>(codebook);
    zero_flag_kernel<<<1, 1>>>();
    gemm_mma_kernel<<<MROWS / BM, GEMM_THREADS, GEMM_SMEM>>>(outI);
    rescore_part_kernel<<<1024, 256>>>(codebook);
    rescore_combine_kernel<<<MROWS / 256, 256>>>(outI);
    embed_mean_kernel<<<dim3(BATCH, 2), 256>>>(embeddings, outR, outL);
    vsa_kernel<<<dim3(BATCH, 2), 256>>>(cbv, roles, outV);
}

// round 8
// speedup vs baseline: 5.4584x; 1.0179x over previous
#include <cuda_runtime.h>
#include <cuda_fp16.h>
#include <cstdint>

// ===========================================================================
// VQPatchEncoder — single-term fp16 mma.sync GEMM + DELTA-certified exact
// argmax. R8: B/A tile fills via cp.async.bulk + mbarrier (1 instr per chunk
// instead of 1024 LDGSTS), swizzle pre-baked into GMEM scratch layouts.
// Compute loop identical to R7.
// ===========================================================================

#define BATCH 1024
#define NP    64
#define PD    192
#define KC    4096
#define ED    2048
#define VD    2048
#define MROWS (BATCH * NP)      // 65536
#define BM    128
#define BN    128
#define KCH   64
#define NCHUNK (PD / KCH)        // 3
#define NTILE  (KC / BN)         // 32
#define TOTIT  (NTILE * NCHUNK)  // 96
#define AROWB  (PD * 2)          // 384
#define ASMEM  (BM * AROWB)      // 49152
#define BBUF   (KCH * BN * 2)    // 16384
#define NBUF   3
#define MBAR_OFF (ASMEM + NBUF * BBUF)        // 98304
#define GEMM_SMEM (MBAR_OFF + 64)             // 98368
#define GEMM_THREADS 256
#define DELTA 4e-3f

// ---- device-global scratch ------------------------------------------------
__device__ __align__(16) __half g_a  [(size_t)MROWS * PD];  // granule-swizzled A
__device__ __align__(16) __half g_bsw[(size_t)PD * KC];     // per-(tile,chunk) smem images of B
__device__ float  g_patches[(size_t)MROWS * PD];
__device__ int    g_indices[MROWS];
__device__ int    g_flagged[MROWS];
__device__ int    g_nflag;
__device__ float  g_part_val[(size_t)MROWS * 4];
__device__ int    g_part_idx[(size_t)MROWS * 4];

__device__ __forceinline__ uint32_t smem_u32(const void* p) {
    uint32_t a;
    asm("{ .reg .u64 t; cvta.to.shared.u64 t, %1; cvt.u32.u64 %0, t; }"
        : "=r"(a) : "l"(p));
    return a;
}

#define MBARRIER_INIT(mbar, cnt) \
    asm volatile("mbarrier.init.shared.b64 [%0], %1;" \
                 :: "r"((uint32_t)(mbar)), "r"((uint32_t)(cnt)) : "memory")
#define MBARRIER_EXPECT_TX(mbar, bytes) \
    asm volatile("mbarrier.arrive.expect_tx.shared.b64 _, [%0], %1;" \
                 :: "r"((uint32_t)(mbar)), "r"((uint32_t)(bytes)) : "memory")

#define MBARRIER_WAIT_PARITY(mbar_addr, phase_parity) do {                        \
    uint32_t _mbar = (uint32_t)(mbar_addr);                                       \
    uint32_t _par  = (uint32_t)(phase_parity);                                    \
    uint32_t _done;                                                               \
    asm volatile("{\n\t.reg .pred p;\n\t"                                         \
        "mbarrier.try_wait.parity.acquire.cta.shared::cta.b64 p, [%1], %2;\n\t"   \
        "selp.b32 %0, 1, 0, p;\n\t}"                                              \
        : "=r"(_done) : "r"(_mbar), "r"(_par) : "memory");                        \
    if (!_done) {                                                                 \
        asm volatile("{\n\t.reg .pred P1;\n\t"                                    \
            "WAIT_LOOP_%=:\n\t"                                                   \
            "mbarrier.try_wait.parity.acquire.cta.shared::cta.b64 P1, [%0], %1, 0x989680;\n\t" \
            "@P1 bra.uni WAIT_DONE_%=;\n\t"                                       \
            "bra.uni WAIT_LOOP_%=;\n\t"                                           \
            "WAIT_DONE_%=:\n\t}"                                                  \
            :: "r"(_mbar), "r"(_par) : "memory");                                 \
    }                                                                             \
} while (0)

__device__ __forceinline__ void bulk_cp(uint32_t dst, const void* src,
                                        uint32_t bytes, uint32_t mbar) {
    asm volatile(
        "cp.async.bulk.shared::cta.global.mbarrier::complete_tx::bytes "
        "[%0], [%1], %2, [%3];"
        :: "r"(dst), "l"(src), "r"(bytes), "r"(mbar) : "memory");
}

__device__ __forceinline__ void ldsm4(uint32_t* r, uint32_t addr) {
    asm volatile("ldmatrix.sync.aligned.m8n8.x4.shared.b16 {%0,%1,%2,%3}, [%4];"
                 : "=r"(r[0]), "=r"(r[1]), "=r"(r[2]), "=r"(r[3]) : "r"(addr));
}
__device__ __forceinline__ void ldsm4t(uint32_t* r, uint32_t addr) {
    asm volatile("ldmatrix.sync.aligned.m8n8.x4.trans.shared.b16 {%0,%1,%2,%3}, [%4];"
                 : "=r"(r[0]), "=r"(r[1]), "=r"(r[2]), "=r"(r[3]) : "r"(addr));
}
__device__ __forceinline__ void mma16816(float* c, const uint32_t* a,
                                         uint32_t b0, uint32_t b1) {
    asm volatile(
        "mma.sync.aligned.m16n8k16.row.col.f32.f16.f16.f32 "
        "{%0,%1,%2,%3}, {%4,%5,%6,%7}, {%8,%9}, {%0,%1,%2,%3};"
        : "+f"(c[0]), "+f"(c[1]), "+f"(c[2]), "+f"(c[3])
        : "r"(a[0]), "r"(a[1]), "r"(a[2]), "r"(a[3]), "r"(b0), "r"(b1));
}

// ===========================================================================
// 1) Patchify: fp32 copy + fp16 value written GRANULE-SWIZZLED so the GEMM's
//    A tile is a linear 48KB image: byte offset m*384 + ((g^(m&7))*16) + (d&7)*2.
// ===========================================================================
__global__ void patchify_split_kernel(const float* __restrict__ pixels) {
    int idx = blockIdx.x * blockDim.x + threadIdx.x;
    if (idx >= MROWS * PD) return;
    int d = idx % PD;
    int m = idx / PD;
    int p = m % NP, b = m / NP;
    int ch = d >> 6;
    int rem = d & 63;
    int pr = rem >> 3, pc = rem & 7;
    int r = p >> 3, c = p & 7;
    float v = pixels[(((size_t)b * 3 + ch) * 64 + (r * 8 + pr)) * 64 + (c * 8 + pc)];
    g_patches[idx] = v;
    int g = d >> 3;
    int sw = (g ^ (m & 7)) * 8 + (d & 7);     // half-index within row
    g_a[(size_t)m * PD + sw] = __float2half_rn(v);
}

// ===========================================================================
// 2) Codebook -> fp16, laid out as the exact smem chunk images:
//    for tile t (codes t*128..), chunk kc (k rows kc*64..): 16KB block at
//    (t*3+kc)*16384 with byte offset r*256 + ((g^(r&7))*16) + (nt&7)*2,
//    r = k within chunk, nt = code within tile, g = nt>>3.
// ===========================================================================
__global__ void split_codebook_kernel(const float* __restrict__ cb) {
    int idx = blockIdx.x * blockDim.x + threadIdx.x;
    if (idx >= PD * KC) return;
    int n = idx % KC;
    int d = idx / KC;
    int t = n >> 7, nt = n & 127;
    int kc = d >> 6, r = d & 63;
    int g = nt >> 3;
    size_t half_off = (size_t)(t * 3 + kc) * 8192
                    + r * 128 + ((g ^ (r & 7)) * 8) + (nt & 7);
    g_bsw[half_off] = __float2half_rn(cb[(size_t)n * PD + d]);
}

__global__ void zero_flag_kernel() { g_nflag = 0; }

// ===========================================================================
// 3) fp16 mma.sync GEMM + fused top-2 argmax. Tile fills via cp.async.bulk.
// ===========================================================================
__global__ __launch_bounds__(GEMM_THREADS, 2) void gemm_mma_kernel(float* __restrict__ outI) {
    extern __shared__ char smem[];
    const uint32_t sA = smem_u32(smem);
    const uint32_t sB = sA + ASMEM;
    const uint32_t mbA = sA + MBAR_OFF;       // A barrier
    const uint32_t mbB = sA + MBAR_OFF + 8;   // 3 B barriers (8B each)
    const int tid = threadIdx.x;
    const int wid = tid >> 5;
    const int lane = tid & 31;
    const int wm = wid >> 2;
    const int wn = wid & 3;
    const int m0 = blockIdx.x * BM;

    if (tid == 0) {
        MBARRIER_INIT(mbA, 1);
        MBARRIER_INIT(mbB + 0, 1);
        MBARRIER_INIT(mbB + 8, 1);
        MBARRIER_INIT(mbB + 16, 1);
    }
    __syncthreads();

    if (tid == 0) {
        MBARRIER_EXPECT_TX(mbA, ASMEM);
        bulk_cp(sA, (const char*)g_a + (size_t)m0 * AROWB, ASMEM, mbA);
        MBARRIER_EXPECT_TX(mbB + 0, BBUF);
        bulk_cp(sB, (const char*)g_bsw, BBUF, mbB + 0);
        MBARRIER_EXPECT_TX(mbB + 8, BBUF);
        bulk_cp(sB + BBUF, (const char*)g_bsw + BBUF, BBUF, mbB + 8);
    }

    float acc[4][2][2][4];
#pragma unroll
    for (int a = 0; a < 4; a++)
#pragma unroll
        for (int b = 0; b < 2; b++)
#pragma unroll
            for (int c = 0; c < 2; c++)
#pragma unroll
                for (int d = 0; d < 4; d++) acc[a][b][c][d] = 0.0f;

    float b1[8], b2[8];
    int   i1[8];
#pragma unroll
    for (int s = 0; s < 8; s++) { b1[s] = -3.0e38f; b2[s] = -3.0e38f; i1[s] = 0; }

    MBARRIER_WAIT_PARITY(mbA, 0);

    for (int it = 0; it < TOTIT; ++it) {
        const int kc = it % NCHUNK;
        const int slot = it % NBUF;
        // chunk it resident?
        MBARRIER_WAIT_PARITY(mbB + slot * 8, (it / NBUF) & 1);
        // all warps done with chunk it-1 (whose slot == (it+2)%NBUF)
        __syncthreads();
        // prefetch chunk it+2 into the freed slot
        if (tid == 0 && it + 2 < TOTIT) {
            int s2 = (it + 2) % NBUF;
            MBARRIER_EXPECT_TX(mbB + s2 * 8, BBUF);
            bulk_cp(sB + s2 * BBUF, (const char*)g_bsw + (size_t)(it + 2) * BBUF,
                    BBUF, mbB + s2 * 8);
        }

        const uint32_t bbuf = sB + slot * BBUF;
#pragma unroll
        for (int kk = 0; kk < 4; kk++) {
            uint32_t afr[4][4];
#pragma unroll
            for (int mm = 0; mm < 4; mm++) {
                int r = wm * 64 + mm * 16 + (lane & 15);
                int g = kc * 8 + kk * 2 + (lane >> 4);
                ldsm4(afr[mm], sA + r * AROWB + ((g ^ (r & 7)) * 16));
            }
#pragma unroll
            for (int nn2 = 0; nn2 < 2; nn2++) {
                int krow = kk * 16 + (lane & 7) + ((lane & 16) ? 8 : 0);
                int g = wn * 4 + nn2 * 2 + ((lane >> 3) & 1);
                uint32_t bfr[4];
                ldsm4t(bfr, bbuf + krow * (BN * 2) + ((g ^ (krow & 7)) * 16));
#pragma unroll
                for (int mm = 0; mm < 4; mm++) {
                    mma16816(acc[mm][nn2][0], afr[mm], bfr[0], bfr[2]);
                    mma16816(acc[mm][nn2][1], afr[mm], bfr[1], bfr[3]);
                }
            }
        }

        if (kc == NCHUNK - 1) {
            const int colb = (it / NCHUNK) * BN + wn * 32 + 2 * (lane & 3);
#pragma unroll
            for (int s = 0; s < 8; s++) {
                const int mm = s >> 1, h = s & 1;
#pragma unroll
                for (int nn2 = 0; nn2 < 2; nn2++) {
#pragma unroll
                    for (int hn = 0; hn < 2; hn++) {
                        int cb = colb + nn2 * 16 + hn * 8;
                        float v0 = acc[mm][nn2][hn][h * 2];
                        if (v0 > b1[s]) { b2[s] = b1[s]; b1[s] = v0; i1[s] = cb; }
                        else if (v0 > b2[s]) b2[s] = v0;
                        float v1 = acc[mm][nn2][hn][h * 2 + 1];
                        if (v1 > b1[s]) { b2[s] = b1[s]; b1[s] = v1; i1[s] = cb + 1; }
                        else if (v1 > b2[s]) b2[s] = v1;
                        acc[mm][nn2][hn][h * 2] = 0.0f;
                        acc[mm][nn2][hn][h * 2 + 1] = 0.0f;
                    }
                }
            }
        }
    }

#pragma unroll
    for (int s = 0; s < 8; s++) {
#pragma unroll
        for (int ofs = 1; ofs <= 2; ofs <<= 1) {
            float w1 = __shfl_xor_sync(0xFFFFFFFFu, b1[s], ofs);
            float w2 = __shfl_xor_sync(0xFFFFFFFFu, b2[s], ofs);
            int   k1 = __shfl_xor_sync(0xFFFFFFFFu, i1[s], ofs);
            if (w1 > b1[s] || (w1 == b1[s] && k1 < i1[s])) {
                b2[s] = fmaxf(b1[s], w2); b1[s] = w1; i1[s] = k1;
            } else {
                b2[s] = fmaxf(b2[s], w1);
            }
        }
    }

    __syncthreads();
    float* rv1 = (float*)(smem + ASMEM);
    float* rv2 = rv1 + BM * 4;
    int*   ri1 = (int*)(rv2 + BM * 4);
    if ((lane & 3) == 0) {
#pragma unroll
        for (int s = 0; s < 8; s++) {
            int row = wm * 64 + (s >> 1) * 16 + (s & 1) * 8 + (lane >> 2);
            rv1[row * 4 + wn] = b1[s];
            rv2[row * 4 + wn] = b2[s];
            ri1[row * 4 + wn] = i1[s];
        }
    }
    __syncthreads();
    if (tid < BM) {
        float v1 = rv1[tid * 4], v2 = rv2[tid * 4];
        int   j1 = ri1[tid * 4];
#pragma unroll
        for (int t = 1; t < 4; t++) {
            float w1 = rv1[tid * 4 + t], w2 = rv2[tid * 4 + t];
            int   k1 = ri1[tid * 4 + t];
            if (w1 > v1 || (w1 == v1 && k1 < j1)) { v2 = fmaxf(v1, w2); v1 = w1; j1 = k1; }
            else v2 = fmaxf(v2, w1);
        }
        int row = m0 + tid;
        g_indices[row] = j1;
        outI[row] = (float)j1;
        if (v1 - v2 < DELTA) {
            int s = atomicAdd(&g_nflag, 1);
            g_flagged[s] = row;
        }
    }
}

// ===========================================================================
// 4a) Tiled batch rescore, bank-conflict-free (unchanged from R7).
// ===========================================================================
__global__ __launch_bounds__(256) void rescore_part_kernel(const float* __restrict__ cb) {
    __shared__ float4 sp[48][20];
    __shared__ float  rv[16][16];
    __shared__ int    ri[16][16];
    const int nf = g_nflag;
    if (nf == 0) return;
    const int ngroups = (nf + 15) >> 4;
    const int nitems = ngroups * 4;
    const int tid = threadIdx.x;
    const int r = tid & 15;
    const int cl = tid >> 4;

    for (int item = blockIdx.x; item < nitems; item += gridDim.x) {
        const int g = item >> 2;
        const int s = item & 3;
        __syncthreads();
        for (int i = tid; i < 16 * 48; i += 256) {
            int rr = i / 48, qq = i % 48;
            int f = g * 16 + rr;
            int m = g_flagged[(f < nf) ? f : (nf - 1)];
            sp[qq][rr] = ((const float4*)(g_patches + (size_t)m * PD))[qq];
        }
        __syncthreads();

        float bv = -3.0e38f;
        int bi = 0;
        const int kbase = s * 1024 + cl * 64;
        for (int j = 0; j < 64; j++) {
            const int k = kbase + j;
            const float4* crow = (const float4*)(cb + (size_t)k * PD);
            float acc = 0.0f;
#pragma unroll 12
            for (int q = 0; q < 48; q++) {
                float4 c4 = crow[q];
                float4 p4 = sp[q][r];
                acc = fmaf(p4.x, c4.x, acc);
                acc = fmaf(p4.y, c4.y, acc);
                acc = fmaf(p4.z, c4.z, acc);
                acc = fmaf(p4.w, c4.w, acc);
            }
            if (acc > bv) { bv = acc; bi = k; }
        }
        rv[r][cl] = bv;
        ri[r][cl] = bi;
        __syncthreads();
        if (tid < 16) {
            float v = rv[tid][0];
            int ix = ri[tid][0];
#pragma unroll
            for (int t = 1; t < 16; t++) {
                float w = rv[tid][t];
                int k1 = ri[tid][t];
                if (w > v || (w == v && k1 < ix)) { v = w; ix = k1; }
            }
            int f = g * 16 + tid;
            if (f < nf) {
                g_part_val[(size_t)f * 4 + s] = v;
                g_part_idx[(size_t)f * 4 + s] = ix;
            }
        }
    }
}

__global__ void rescore_combine_kernel(float* __restrict__ outI) {
    int f = blockIdx.x * blockDim.x + threadIdx.x;
    if (f >= g_nflag) return;
    float bv = g_part_val[(size_t)f * 4];
    int bi = g_part_idx[(size_t)f * 4];
#pragma unroll
    for (int s = 1; s < 4; s++) {
        float v = g_part_val[(size_t)f * 4 + s];
        int ix = g_part_idx[(size_t)f * 4 + s];
        if (v > bv || (v == bv && ix < bi)) { bv = v; bi = ix; }
    }
    int m = g_flagged[f];
    g_indices[m] = bi;
    outI[m] = (float)bi;
}

// ===========================================================================
// 5) Embedding means, float4.
// ===========================================================================
__global__ __launch_bounds__(256) void embed_mean_kernel(
    const float* __restrict__ emb, float* __restrict__ outR, float* __restrict__ outL)
{
    const int b = blockIdx.x;
    __shared__ int sIdx[NP];
    if (threadIdx.x < NP) sIdx[threadIdx.x] = g_indices[b * NP + threadIdx.x];
    __syncthreads();
    const int e4 = blockIdx.y * 256 + threadIdx.x;
    const float4* emb4 = (const float4*)emb;
    float4 s = make_float4(0.f, 0.f, 0.f, 0.f);
    float4 sl = make_float4(0.f, 0.f, 0.f, 0.f);
#pragma unroll 8
    for (int p = 0; p < NP; p++) {
        float4 v = emb4[(size_t)sIdx[p] * (ED / 4) + e4];
        s.x += v.x; s.y += v.y; s.z += v.z; s.w += v.w;
        int r = p >> 3, c = p & 7;
        if (r >= 3 && r < 6 && c >= 3 && c < 6) {
            sl.x += v.x; sl.y += v.y; sl.z += v.z; sl.w += v.w;
        }
    }
    const float iR = 1.0f / 64.0f, iL = 1.0f / 9.0f;
    ((float4*)outR)[(size_t)b * (ED / 4) + e4] =
        make_float4(s.x * iR, s.y * iR, s.z * iR, s.w * iR);
    ((float4*)outL)[(size_t)b * (ED / 4) + e4] =
        make_float4(sl.x * iL, sl.y * iL, sl.z * iL, sl.w * iL);
}

// ===========================================================================
// 6) VSA, float4.
// ===========================================================================
__global__ __launch_bounds__(256) void vsa_kernel(
    const float* __restrict__ cbv, const float* __restrict__ roles,
    float* __restrict__ outV)
{
    const int b = blockIdx.x;
    __shared__ int sIdx[16];
    __shared__ int sPos[16];
    if (threadIdx.x < 16) {
        int r = 2 + (threadIdx.x >> 2);
        int c = 2 + (threadIdx.x & 3);
        int p = r * 8 + c;
        sPos[threadIdx.x] = p;
        sIdx[threadIdx.x] = g_indices[b * NP + p];
    }
    __syncthreads();
    const int v4 = blockIdx.y * 256 + threadIdx.x;
    const float4* cbv4 = (const float4*)cbv;
    const float4* rol4 = (const float4*)roles;
    int cx = 0, cy = 0, cz = 0, cw = 0;
#pragma unroll
    for (int t = 0; t < 16; t++) {
        float4 a = cbv4[(size_t)sIdx[t] * (VD / 4) + v4];
        float4 q = rol4[(size_t)sPos[t] * (VD / 4) + v4];
        cx += (a.x != q.x); cy += (a.y != q.y);
        cz += (a.z != q.z); cw += (a.w != q.w);
    }
    ((float4*)outV)[(size_t)b * (VD / 4) + v4] =
        make_float4(cx > 8 ? 1.f : 0.f, cy > 8 ? 1.f : 0.f,
                    cz > 8 ? 1.f : 0.f, cw > 8 ? 1.f : 0.f);
}

// ===========================================================================
extern "C" void kernel_launch(void* const* d_in, const int* in_sizes, int n_in,
                              void* d_out, int out_size)
{
    const float* pixels     = (const float*)d_in[0];
    const float* codebook   = (const float*)d_in[1];
    const float* embeddings = (const float*)d_in[2];
    const float* cbv        = (const float*)d_in[3];
    const float* roles      = (const float*)d_in[4];

    float* out  = (float*)d_out;
    float* outR = out;
    float* outV = out + (size_t)BATCH * ED;
    float* outI = out + 2 * (size_t)BATCH * ED;
    float* outL = out + 2 * (size_t)BATCH * ED + (size_t)BATCH * NP;

    static bool attr_set = false;
    if (!attr_set) {
        cudaFuncSetAttribute(gemm_mma_kernel,
                             cudaFuncAttributeMaxDynamicSharedMemorySize, GEMM_SMEM);
        attr_set = true;
    }

    patchify_split_kernel<<<(MROWS * PD + 255) / 256, 256>>>(pixels);
    split_codebook_kernel<<<(PD * KC + 255) / 256, 256>>>(codebook);
    zero_flag_kernel<<<1, 1>>>();
    gemm_mma_kernel<<<MROWS / BM, GEMM_THREADS, GEMM_SMEM>>>(outI);
    rescore_part_kernel<<<1024, 256>>>(codebook);
    rescore_combine_kernel<<<MROWS / 256, 256>>>(outI);
    embed_mean_kernel<<<dim3(BATCH, 2), 256>>>(embeddings, outR, outL);
    vsa_kernel<<<dim3(BATCH, 2), 256>>>(cbv, roles, outV);
}

// round 9
// speedup vs baseline: 5.4886x; 1.0055x over previous
#include <cuda_runtime.h>
#include <cuda_fp16.h>
#include <cstdint>

// ===========================================================================
// VQPatchEncoder — single-term fp16 mma.sync GEMM + DELTA-certified exact
// argmax. R9: BN 128->64, 3 CTAs/SM (6 warps/SMSP) to fix the latency-
// hiding shortfall diagnosed in R8. Pipeline/swizzle/rescore unchanged.
// ===========================================================================

#define BATCH 1024
#define NP    64
#define PD    192
#define KC    4096
#define ED    2048
#define VD    2048
#define MROWS (BATCH * NP)      // 65536
#define BM    128
#define BN    64
#define KCH   64
#define NCHUNK (PD / KCH)        // 3
#define NTILE  (KC / BN)         // 64
#define TOTIT  (NTILE * NCHUNK)  // 192
#define AROWB  (PD * 2)          // 384
#define ASMEM  (BM * AROWB)      // 49152
#define BBUF   (KCH * BN * 2)    // 8192
#define NBUF   3
#define MBAR_OFF (ASMEM + NBUF * BBUF)        // 73728
#define GEMM_SMEM (MBAR_OFF + 64)             // 73792
#define GEMM_THREADS 256
#define DELTA 4e-3f

// ---- device-global scratch ------------------------------------------------
__device__ __align__(16) __half g_a  [(size_t)MROWS * PD];  // granule-swizzled A
__device__ __align__(16) __half g_bsw[(size_t)PD * KC];     // per-(tile,chunk) smem images of B
__device__ float  g_patches[(size_t)MROWS * PD];
__device__ int    g_indices[MROWS];
__device__ int    g_flagged[MROWS];
__device__ int    g_nflag;
__device__ float  g_part_val[(size_t)MROWS * 4];
__device__ int    g_part_idx[(size_t)MROWS * 4];

__device__ __forceinline__ uint32_t smem_u32(const void* p) {
    uint32_t a;
    asm("{ .reg .u64 t; cvta.to.shared.u64 t, %1; cvt.u32.u64 %0, t; }"
        : "=r"(a) : "l"(p));
    return a;
}

#define MBARRIER_INIT(mbar, cnt) \
    asm volatile("mbarrier.init.shared.b64 [%0], %1;" \
                 :: "r"((uint32_t)(mbar)), "r"((uint32_t)(cnt)) : "memory")
#define MBARRIER_EXPECT_TX(mbar, bytes) \
    asm volatile("mbarrier.arrive.expect_tx.shared.b64 _, [%0], %1;" \
                 :: "r"((uint32_t)(mbar)), "r"((uint32_t)(bytes)) : "memory")

#define MBARRIER_WAIT_PARITY(mbar_addr, phase_parity) do {                        \
    uint32_t _mbar = (uint32_t)(mbar_addr);                                       \
    uint32_t _par  = (uint32_t)(phase_parity);                                    \
    uint32_t _done;                                                               \
    asm volatile("{\n\t.reg .pred p;\n\t"                                         \
        "mbarrier.try_wait.parity.acquire.cta.shared::cta.b64 p, [%1], %2;\n\t"   \
        "selp.b32 %0, 1, 0, p;\n\t}"                                              \
        : "=r"(_done) : "r"(_mbar), "r"(_par) : "memory");                        \
    if (!_done) {                                                                 \
        asm volatile("{\n\t.reg .pred P1;\n\t"                                    \
            "WAIT_LOOP_%=:\n\t"                                                   \
            "mbarrier.try_wait.parity.acquire.cta.shared::cta.b64 P1, [%0], %1, 0x989680;\n\t" \
            "@P1 bra.uni WAIT_DONE_%=;\n\t"                                       \
            "bra.uni WAIT_LOOP_%=;\n\t"                                           \
            "WAIT_DONE_%=:\n\t}"                                                  \
            :: "r"(_mbar), "r"(_par) : "memory");                                 \
    }                                                                             \
} while (0)

__device__ __forceinline__ void bulk_cp(uint32_t dst, const void* src,
                                        uint32_t bytes, uint32_t mbar) {
    asm volatile(
        "cp.async.bulk.shared::cta.global.mbarrier::complete_tx::bytes "
        "[%0], [%1], %2, [%3];"
        :: "r"(dst), "l"(src), "r"(bytes), "r"(mbar) : "memory");
}

__device__ __forceinline__ void ldsm4(uint32_t* r, uint32_t addr) {
    asm volatile("ldmatrix.sync.aligned.m8n8.x4.shared.b16 {%0,%1,%2,%3}, [%4];"
                 : "=r"(r[0]), "=r"(r[1]), "=r"(r[2]), "=r"(r[3]) : "r"(addr));
}
__device__ __forceinline__ void ldsm4t(uint32_t* r, uint32_t addr) {
    asm volatile("ldmatrix.sync.aligned.m8n8.x4.trans.shared.b16 {%0,%1,%2,%3}, [%4];"
                 : "=r"(r[0]), "=r"(r[1]), "=r"(r[2]), "=r"(r[3]) : "r"(addr));
}
__device__ __forceinline__ void mma16816(float* c, const uint32_t* a,
                                         uint32_t b0, uint32_t b1) {
    asm volatile(
        "mma.sync.aligned.m16n8k16.row.col.f32.f16.f16.f32 "
        "{%0,%1,%2,%3}, {%4,%5,%6,%7}, {%8,%9}, {%0,%1,%2,%3};"
        : "+f"(c[0]), "+f"(c[1]), "+f"(c[2]), "+f"(c[3])
        : "r"(a[0]), "r"(a[1]), "r"(a[2]), "r"(a[3]), "r"(b0), "r"(b1));
}

// ===========================================================================
// 1) Patchify: fp32 copy + granule-swizzled fp16 A rows.
// ===========================================================================
__global__ void patchify_split_kernel(const float* __restrict__ pixels) {
    int idx = blockIdx.x * blockDim.x + threadIdx.x;
    if (idx >= MROWS * PD) return;
    int d = idx % PD;
    int m = idx / PD;
    int p = m % NP, b = m / NP;
    int ch = d >> 6;
    int rem = d & 63;
    int pr = rem >> 3, pc = rem & 7;
    int r = p >> 3, c = p & 7;
    float v = pixels[(((size_t)b * 3 + ch) * 64 + (r * 8 + pr)) * 64 + (c * 8 + pc)];
    g_patches[idx] = v;
    int g = d >> 3;
    int sw = (g ^ (m & 7)) * 8 + (d & 7);
    g_a[(size_t)m * PD + sw] = __float2half_rn(v);
}

// ===========================================================================
// 2) Codebook -> fp16 smem chunk images, BN=64-wide tiles.
//    Block (t*3+kc) of 8KB: offset r*128 + ((g^(r&7))*8 + (nt&7)) halves,
//    r = k within chunk (0..63), nt = n&63, g = nt>>3 (0..7).
// ===========================================================================
__global__ void split_codebook_kernel(const float* __restrict__ cb) {
    int idx = blockIdx.x * blockDim.x + threadIdx.x;
    if (idx >= PD * KC) return;
    int n = idx % KC;
    int d = idx / KC;
    int t = n >> 6, nt = n & 63;
    int kc = d >> 6, r = d & 63;
    int g = nt >> 3;
    size_t half_off = (size_t)(t * 3 + kc) * 4096
                    + r * 64 + ((g ^ (r & 7)) * 8) + (nt & 7);
    g_bsw[half_off] = __float2half_rn(cb[(size_t)n * PD + d]);
}

__global__ void zero_flag_kernel() { g_nflag = 0; }

// ===========================================================================
// 3) fp16 mma.sync GEMM + fused top-2 argmax. 8 warps: wm 0..3 (32 M rows),
//    wn 0..1 (32 N cols). 3 CTAs/SM.
// ===========================================================================
__global__ __launch_bounds__(GEMM_THREADS, 3) void gemm_mma_kernel(float* __restrict__ outI) {
    extern __shared__ char smem[];
    const uint32_t sA = smem_u32(smem);
    const uint32_t sB = sA + ASMEM;
    const uint32_t mbA = sA + MBAR_OFF;
    const uint32_t mbB = sA + MBAR_OFF + 8;
    const int tid = threadIdx.x;
    const int wid = tid >> 5;
    const int lane = tid & 31;
    const int wm = wid >> 1;    // 0..3
    const int wn = wid & 1;     // 0..1
    const int m0 = blockIdx.x * BM;

    if (tid == 0) {
        MBARRIER_INIT(mbA, 1);
        MBARRIER_INIT(mbB + 0, 1);
        MBARRIER_INIT(mbB + 8, 1);
        MBARRIER_INIT(mbB + 16, 1);
    }
    __syncthreads();

    if (tid == 0) {
        MBARRIER_EXPECT_TX(mbA, ASMEM);
        bulk_cp(sA, (const char*)g_a + (size_t)m0 * AROWB, ASMEM, mbA);
        MBARRIER_EXPECT_TX(mbB + 0, BBUF);
        bulk_cp(sB, (const char*)g_bsw, BBUF, mbB + 0);
        MBARRIER_EXPECT_TX(mbB + 8, BBUF);
        bulk_cp(sB + BBUF, (const char*)g_bsw + BBUF, BBUF, mbB + 8);
    }

    float acc[2][2][2][4];
#pragma unroll
    for (int a = 0; a < 2; a++)
#pragma unroll
        for (int b = 0; b < 2; b++)
#pragma unroll
            for (int c = 0; c < 2; c++)
#pragma unroll
                for (int d = 0; d < 4; d++) acc[a][b][c][d] = 0.0f;

    float b1[4], b2[4];
    int   i1[4];
#pragma unroll
    for (int s = 0; s < 4; s++) { b1[s] = -3.0e38f; b2[s] = -3.0e38f; i1[s] = 0; }

    MBARRIER_WAIT_PARITY(mbA, 0);

    for (int it = 0; it < TOTIT; ++it) {
        const int kc = it % NCHUNK;
        const int slot = it % NBUF;
        MBARRIER_WAIT_PARITY(mbB + slot * 8, (it / NBUF) & 1);
        __syncthreads();
        if (tid == 0 && it + 2 < TOTIT) {
            int s2 = (it + 2) % NBUF;
            MBARRIER_EXPECT_TX(mbB + s2 * 8, BBUF);
            bulk_cp(sB + s2 * BBUF, (const char*)g_bsw + (size_t)(it + 2) * BBUF,
                    BBUF, mbB + s2 * 8);
        }

        const uint32_t bbuf = sB + slot * BBUF;
#pragma unroll
        for (int kk = 0; kk < 4; kk++) {
            uint32_t afr[2][4];
#pragma unroll
            for (int mm = 0; mm < 2; mm++) {
                int r = wm * 32 + mm * 16 + (lane & 15);
                int g = kc * 8 + kk * 2 + (lane >> 4);
                ldsm4(afr[mm], sA + r * AROWB + ((g ^ (r & 7)) * 16));
            }
#pragma unroll
            for (int nn2 = 0; nn2 < 2; nn2++) {
                int krow = kk * 16 + (lane & 7) + ((lane & 16) ? 8 : 0);
                int g = wn * 4 + nn2 * 2 + ((lane >> 3) & 1);
                uint32_t bfr[4];
                // B row = 64 codes * 2B = 128 B
                ldsm4t(bfr, bbuf + krow * (BN * 2) + ((g ^ (krow & 7)) * 16));
#pragma unroll
                for (int mm = 0; mm < 2; mm++) {
                    mma16816(acc[mm][nn2][0], afr[mm], bfr[0], bfr[2]);
                    mma16816(acc[mm][nn2][1], afr[mm], bfr[1], bfr[3]);
                }
            }
        }

        if (kc == NCHUNK - 1) {
            const int colb = (it / NCHUNK) * BN + wn * 32 + 2 * (lane & 3);
#pragma unroll
            for (int s = 0; s < 4; s++) {
                const int mm = s >> 1, h = s & 1;
#pragma unroll
                for (int nn2 = 0; nn2 < 2; nn2++) {
#pragma unroll
                    for (int hn = 0; hn < 2; hn++) {
                        int cb = colb + nn2 * 16 + hn * 8;
                        float v0 = acc[mm][nn2][hn][h * 2];
                        if (v0 > b1[s]) { b2[s] = b1[s]; b1[s] = v0; i1[s] = cb; }
                        else if (v0 > b2[s]) b2[s] = v0;
                        float v1 = acc[mm][nn2][hn][h * 2 + 1];
                        if (v1 > b1[s]) { b2[s] = b1[s]; b1[s] = v1; i1[s] = cb + 1; }
                        else if (v1 > b2[s]) b2[s] = v1;
                        acc[mm][nn2][hn][h * 2] = 0.0f;
                        acc[mm][nn2][hn][h * 2 + 1] = 0.0f;
                    }
                }
            }
        }
    }

    // ---- quad-lane merge ----
#pragma unroll
    for (int s = 0; s < 4; s++) {
#pragma unroll
        for (int ofs = 1; ofs <= 2; ofs <<= 1) {
            float w1 = __shfl_xor_sync(0xFFFFFFFFu, b1[s], ofs);
            float w2 = __shfl_xor_sync(0xFFFFFFFFu, b2[s], ofs);
            int   k1 = __shfl_xor_sync(0xFFFFFFFFu, i1[s], ofs);
            if (w1 > b1[s] || (w1 == b1[s] && k1 < i1[s])) {
                b2[s] = fmaxf(b1[s], w2); b1[s] = w1; i1[s] = k1;
            } else {
                b2[s] = fmaxf(b2[s], w1);
            }
        }
    }

    // ---- cross-warp reduction via smem (reuse B buffers) ----
    __syncthreads();
    float* rv1 = (float*)(smem + ASMEM);
    float* rv2 = rv1 + BM * 2;
    int*   ri1 = (int*)(rv2 + BM * 2);
    if ((lane & 3) == 0) {
#pragma unroll
        for (int s = 0; s < 4; s++) {
            int row = wm * 32 + (s >> 1) * 16 + (s & 1) * 8 + (lane >> 2);
            rv1[row * 2 + wn] = b1[s];
            rv2[row * 2 + wn] = b2[s];
            ri1[row * 2 + wn] = i1[s];
        }
    }
    __syncthreads();
    if (tid < BM) {
        float v1 = rv1[tid * 2], v2 = rv2[tid * 2];
        int   j1 = ri1[tid * 2];
        float w1 = rv1[tid * 2 + 1], w2 = rv2[tid * 2 + 1];
        int   k1 = ri1[tid * 2 + 1];
        if (w1 > v1 || (w1 == v1 && k1 < j1)) { v2 = fmaxf(v1, w2); v1 = w1; j1 = k1; }
        else v2 = fmaxf(v2, w1);
        int row = m0 + tid;
        g_indices[row] = j1;
        outI[row] = (float)j1;
        if (v1 - v2 < DELTA) {
            int s = atomicAdd(&g_nflag, 1);
            g_flagged[s] = row;
        }
    }
}

// ===========================================================================
// 4a) Tiled batch rescore, bank-conflict-free (unchanged from R7).
// ===========================================================================
__global__ __launch_bounds__(256) void rescore_part_kernel(const float* __restrict__ cb) {
    __shared__ float4 sp[48][20];
    __shared__ float  rv[16][16];
    __shared__ int    ri[16][16];
    const int nf = g_nflag;
    if (nf == 0) return;
    const int ngroups = (nf + 15) >> 4;
    const int nitems = ngroups * 4;
    const int tid = threadIdx.x;
    const int r = tid & 15;
    const int cl = tid >> 4;

    for (int item = blockIdx.x; item < nitems; item += gridDim.x) {
        const int g = item >> 2;
        const int s = item & 3;
        __syncthreads();
        for (int i = tid; i < 16 * 48; i += 256) {
            int rr = i / 48, qq = i % 48;
            int f = g * 16 + rr;
            int m = g_flagged[(f < nf) ? f : (nf - 1)];
            sp[qq][rr] = ((const float4*)(g_patches + (size_t)m * PD))[qq];
        }
        __syncthreads();

        float bv = -3.0e38f;
        int bi = 0;
        const int kbase = s * 1024 + cl * 64;
        for (int j = 0; j < 64; j++) {
            const int k = kbase + j;
            const float4* crow = (const float4*)(cb + (size_t)k * PD);
            float acc = 0.0f;
#pragma unroll 12
            for (int q = 0; q < 48; q++) {
                float4 c4 = crow[q];
                float4 p4 = sp[q][r];
                acc = fmaf(p4.x, c4.x, acc);
                acc = fmaf(p4.y, c4.y, acc);
                acc = fmaf(p4.z, c4.z, acc);
                acc = fmaf(p4.w, c4.w, acc);
            }
            if (acc > bv) { bv = acc; bi = k; }
        }
        rv[r][cl] = bv;
        ri[r][cl] = bi;
        __syncthreads();
        if (tid < 16) {
            float v = rv[tid][0];
            int ix = ri[tid][0];
#pragma unroll
            for (int t = 1; t < 16; t++) {
                float w = rv[tid][t];
                int k1 = ri[tid][t];
                if (w > v || (w == v && k1 < ix)) { v = w; ix = k1; }
            }
            int f = g * 16 + tid;
            if (f < nf) {
                g_part_val[(size_t)f * 4 + s] = v;
                g_part_idx[(size_t)f * 4 + s] = ix;
            }
        }
    }
}

__global__ void rescore_combine_kernel(float* __restrict__ outI) {
    int f = blockIdx.x * blockDim.x + threadIdx.x;
    if (f >= g_nflag) return;
    float bv = g_part_val[(size_t)f * 4];
    int bi = g_part_idx[(size_t)f * 4];
#pragma unroll
    for (int s = 1; s < 4; s++) {
        float v = g_part_val[(size_t)f * 4 + s];
        int ix = g_part_idx[(size_t)f * 4 + s];
        if (v > bv || (v == bv && ix < bi)) { bv = v; bi = ix; }
    }
    int m = g_flagged[f];
    g_indices[m] = bi;
    outI[m] = (float)bi;
}

// ===========================================================================
// 5) Embedding means, float4.
// ===========================================================================
__global__ __launch_bounds__(256) void embed_mean_kernel(
    const float* __restrict__ emb, float* __restrict__ outR, float* __restrict__ outL)
{
    const int b = blockIdx.x;
    __shared__ int sIdx[NP];
    if (threadIdx.x < NP) sIdx[threadIdx.x] = g_indices[b * NP + threadIdx.x];
    __syncthreads();
    const int e4 = blockIdx.y * 256 + threadIdx.x;
    const float4* emb4 = (const float4*)emb;
    float4 s = make_float4(0.f, 0.f, 0.f, 0.f);
    float4 sl = make_float4(0.f, 0.f, 0.f, 0.f);
#pragma unroll 8
    for (int p = 0; p < NP; p++) {
        float4 v = emb4[(size_t)sIdx[p] * (ED / 4) + e4];
        s.x += v.x; s.y += v.y; s.z += v.z; s.w += v.w;
        int r = p >> 3, c = p & 7;
        if (r >= 3 && r < 6 && c >= 3 && c < 6) {
            sl.x += v.x; sl.y += v.y; sl.z += v.z; sl.w += v.w;
        }
    }
    const float iR = 1.0f / 64.0f, iL = 1.0f / 9.0f;
    ((float4*)outR)[(size_t)b * (ED / 4) + e4] =
        make_float4(s.x * iR, s.y * iR, s.z * iR, s.w * iR);
    ((float4*)outL)[(size_t)b * (ED / 4) + e4] =
        make_float4(sl.x * iL, sl.y * iL, sl.z * iL, sl.w * iL);
}

// ===========================================================================
// 6) VSA, float4.
// ===========================================================================
__global__ __launch_bounds__(256) void vsa_kernel(
    const float* __restrict__ cbv, const float* __restrict__ roles,
    float* __restrict__ outV)
{
    const int b = blockIdx.x;
    __shared__ int sIdx[16];
    __shared__ int sPos[16];
    if (threadIdx.x < 16) {
        int r = 2 + (threadIdx.x >> 2);
        int c = 2 + (threadIdx.x & 3);
        int p = r * 8 + c;
        sPos[threadIdx.x] = p;
        sIdx[threadIdx.x] = g_indices[b * NP + p];
    }
    __syncthreads();
    const int v4 = blockIdx.y * 256 + threadIdx.x;
    const float4* cbv4 = (const float4*)cbv;
    const float4* rol4 = (const float4*)roles;
    int cx = 0, cy = 0, cz = 0, cw = 0;
#pragma unroll
    for (int t = 0; t < 16; t++) {
        float4 a = cbv4[(size_t)sIdx[t] * (VD / 4) + v4];
        float4 q = rol4[(size_t)sPos[t] * (VD / 4) + v4];
        cx += (a.x != q.x); cy += (a.y != q.y);
        cz += (a.z != q.z); cw += (a.w != q.w);
    }
    ((float4*)outV)[(size_t)b * (VD / 4) + v4] =
        make_float4(cx > 8 ? 1.f : 0.f, cy > 8 ? 1.f : 0.f,
                    cz > 8 ? 1.f : 0.f, cw > 8 ? 1.f : 0.f);
}

// ===========================================================================
extern "C" void kernel_launch(void* const* d_in, const int* in_sizes, int n_in,
                              void* d_out, int out_size)
{
    const float* pixels     = (const float*)d_in[0];
    const float* codebook   = (const float*)d_in[1];
    const float* embeddings = (const float*)d_in[2];
    const float* cbv        = (const float*)d_in[3];
    const float* roles      = (const float*)d_in[4];

    float* out  = (float*)d_out;
    float* outR = out;
    float* outV = out + (size_t)BATCH * ED;
    float* outI = out + 2 * (size_t)BATCH * ED;
    float* outL = out + 2 * (size_t)BATCH * ED + (size_t)BATCH * NP;

    static bool attr_set = false;
    if (!attr_set) {
        cudaFuncSetAttribute(gemm_mma_kernel,
                             cudaFuncAttributeMaxDynamicSharedMemorySize, GEMM_SMEM);
        attr_set = true;
    }

    patchify_split_kernel<<<(MROWS * PD + 255) / 256, 256>>>(pixels);
    split_codebook_kernel<<<(PD * KC + 255) / 256, 256>>>(codebook);
    zero_flag_kernel<<<1, 1>>>();
    gemm_mma_kernel<<<MROWS / BM, GEMM_THREADS, GEMM_SMEM>>>(outI);
    rescore_part_kernel<<<1024, 256>>>(codebook);
    rescore_combine_kernel<<<MROWS / 256, 256>>>(outI);
    embed_mean_kernel<<<dim3(BATCH, 2), 256>>>(embeddings, outR, outL);
    vsa_kernel<<<dim3(BATCH, 2), 256>>>(cbv, roles, outV);
}

// round 10
// speedup vs baseline: 5.9812x; 1.0897x over previous
#include <cuda_runtime.h>
#include <cuda_fp16.h>
#include <cstdint>

// ===========================================================================
// VQPatchEncoder — single-term fp16 mma.sync GEMM + DELTA-certified exact
// argmax. R10: full-K tiles (1 sync per N-tile), register double-buffered
// ldsm->mma pipeline, fused prep + fused tail kernels.
// ===========================================================================

#define BATCH 1024
#define NP    64
#define PD    192
#define KC    4096
#define ED    2048
#define VD    2048
#define MROWS (BATCH * NP)      // 65536
#define BM    128
#define BN    64
#define NTILE  (KC / BN)         // 64
#define KSTEPS (PD / 16)         // 12
#define AROWB  (PD * 2)          // 384
#define ASMEM  (BM * AROWB)      // 49152
#define BBUF   (PD * BN * 2)     // 24576 (full-K tile)
#define NBUF   2
#define MBAR_OFF (ASMEM + NBUF * BBUF)        // 98304
#define GEMM_SMEM (MBAR_OFF + 64)             // 98368
#define GEMM_THREADS 256
#define DELTA 4e-3f

// ---- device-global scratch ------------------------------------------------
__device__ __align__(16) __half g_a  [(size_t)MROWS * PD];  // granule-swizzled A
__device__ __align__(16) __half g_bsw[(size_t)PD * KC];     // per-(tile,chunk) smem images
__device__ float  g_patches[(size_t)MROWS * PD];
__device__ int    g_indices[MROWS];
__device__ int    g_flagged[MROWS];
__device__ int    g_nflag;
__device__ float  g_part_val[(size_t)MROWS * 4];
__device__ int    g_part_idx[(size_t)MROWS * 4];

__device__ __forceinline__ uint32_t smem_u32(const void* p) {
    uint32_t a;
    asm("{ .reg .u64 t; cvta.to.shared.u64 t, %1; cvt.u32.u64 %0, t; }"
        : "=r"(a) : "l"(p));
    return a;
}

#define MBARRIER_INIT(mbar, cnt) \
    asm volatile("mbarrier.init.shared.b64 [%0], %1;" \
                 :: "r"((uint32_t)(mbar)), "r"((uint32_t)(cnt)) : "memory")
#define MBARRIER_EXPECT_TX(mbar, bytes) \
    asm volatile("mbarrier.arrive.expect_tx.shared.b64 _, [%0], %1;" \
                 :: "r"((uint32_t)(mbar)), "r"((uint32_t)(bytes)) : "memory")

#define MBARRIER_WAIT_PARITY(mbar_addr, phase_parity) do {                        \
    uint32_t _mbar = (uint32_t)(mbar_addr);                                       \
    uint32_t _par  = (uint32_t)(phase_parity);                                    \
    uint32_t _done;                                                               \
    asm volatile("{\n\t.reg .pred p;\n\t"                                         \
        "mbarrier.try_wait.parity.acquire.cta.shared::cta.b64 p, [%1], %2;\n\t"   \
        "selp.b32 %0, 1, 0, p;\n\t}"                                              \
        : "=r"(_done) : "r"(_mbar), "r"(_par) : "memory");                        \
    if (!_done) {                                                                 \
        asm volatile("{\n\t.reg .pred P1;\n\t"                                    \
            "WAIT_LOOP_%=:\n\t"                                                   \
            "mbarrier.try_wait.parity.acquire.cta.shared::cta.b64 P1, [%0], %1, 0x989680;\n\t" \
            "@P1 bra.uni WAIT_DONE_%=;\n\t"                                       \
            "bra.uni WAIT_LOOP_%=;\n\t"                                           \
            "WAIT_DONE_%=:\n\t}"                                                  \
            :: "r"(_mbar), "r"(_par) : "memory");                                 \
    }                                                                             \
} while (0)

__device__ __forceinline__ void bulk_cp(uint32_t dst, const void* src,
                                        uint32_t bytes, uint32_t mbar) {
    asm volatile(
        "cp.async.bulk.shared::cta.global.mbarrier::complete_tx::bytes "
        "[%0], [%1], %2, [%3];"
        :: "r"(dst), "l"(src), "r"(bytes), "r"(mbar) : "memory");
}

__device__ __forceinline__ void ldsm4(uint32_t* r, uint32_t addr) {
    asm volatile("ldmatrix.sync.aligned.m8n8.x4.shared.b16 {%0,%1,%2,%3}, [%4];"
                 : "=r"(r[0]), "=r"(r[1]), "=r"(r[2]), "=r"(r[3]) : "r"(addr));
}
__device__ __forceinline__ void ldsm4t(uint32_t* r, uint32_t addr) {
    asm volatile("ldmatrix.sync.aligned.m8n8.x4.trans.shared.b16 {%0,%1,%2,%3}, [%4];"
                 : "=r"(r[0]), "=r"(r[1]), "=r"(r[2]), "=r"(r[3]) : "r"(addr));
}
__device__ __forceinline__ void mma16816(float* c, const uint32_t* a,
                                         uint32_t b0, uint32_t b1) {
    asm volatile(
        "mma.sync.aligned.m16n8k16.row.col.f32.f16.f16.f32 "
        "{%0,%1,%2,%3}, {%4,%5,%6,%7}, {%8,%9}, {%0,%1,%2,%3};"
        : "+f"(c[0]), "+f"(c[1]), "+f"(c[2]), "+f"(c[3])
        : "r"(a[0]), "r"(a[1]), "r"(a[2]), "r"(a[3]), "r"(b0), "r"(b1));
}

// ===========================================================================
// 1) Fused prep: patchify (+fp32 copy, granule-swizzled fp16 A), codebook
//    smem-image layout, and flag reset. Partitioned by blockIdx.x.
// ===========================================================================
#define PFY_BLOCKS ((MROWS * PD) / 256)          // 49152
#define CB_BLOCKS  ((PD * KC) / 256)             // 3072
__global__ void prep_kernel(const float* __restrict__ pixels,
                            const float* __restrict__ cbk) {
    int bid = blockIdx.x;
    if (bid < PFY_BLOCKS) {
        int idx = bid * 256 + threadIdx.x;
        int d = idx % PD;
        int m = idx / PD;
        int p = m % NP, b = m / NP;
        int ch = d >> 6;
        int rem = d & 63;
        int pr = rem >> 3, pc = rem & 7;
        int r = p >> 3, c = p & 7;
        float v = pixels[(((size_t)b * 3 + ch) * 64 + (r * 8 + pr)) * 64 + (c * 8 + pc)];
        g_patches[idx] = v;
        int g = d >> 3;
        int sw = (g ^ (m & 7)) * 8 + (d & 7);
        g_a[(size_t)m * PD + sw] = __float2half_rn(v);
    } else if (bid < PFY_BLOCKS + CB_BLOCKS) {
        int idx = (bid - PFY_BLOCKS) * 256 + threadIdx.x;
        int n = idx % KC;
        int d = idx / KC;
        int t = n >> 6, nt = n & 63;
        int kc = d >> 6, r = d & 63;
        int g = nt >> 3;
        size_t half_off = (size_t)(t * 3 + kc) * 4096
                        + r * 64 + ((g ^ (r & 7)) * 8) + (nt & 7);
        g_bsw[half_off] = __float2half_rn(cbk[(size_t)n * PD + d]);
    } else {
        if (threadIdx.x == 0) g_nflag = 0;
    }
}

// ===========================================================================
// 2) fp16 mma.sync GEMM + fused top-2 argmax.
//    Full-K (192) tiles of 64 codes; 1 mbarrier wait + 1 syncthreads per
//    tile; A/B fragments register double-buffered across kk.
// ===========================================================================
__global__ __launch_bounds__(GEMM_THREADS, 2) void gemm_mma_kernel(float* __restrict__ outI) {
    extern __shared__ char smem[];
    const uint32_t sA = smem_u32(smem);
    const uint32_t sB = sA + ASMEM;
    const uint32_t mbA = sA + MBAR_OFF;
    const uint32_t mbB = sA + MBAR_OFF + 8;
    const int tid = threadIdx.x;
    const int wid = tid >> 5;
    const int lane = tid & 31;
    const int wm = wid >> 1;    // 0..3 (32 M rows)
    const int wn = wid & 1;     // 0..1 (32 N cols)
    const int m0 = blockIdx.x * BM;

    if (tid == 0) {
        MBARRIER_INIT(mbA, 1);
        MBARRIER_INIT(mbB + 0, 1);
        MBARRIER_INIT(mbB + 8, 1);
    }
    __syncthreads();

    if (tid == 0) {
        MBARRIER_EXPECT_TX(mbA, ASMEM);
        bulk_cp(sA, (const char*)g_a + (size_t)m0 * AROWB, ASMEM, mbA);
        MBARRIER_EXPECT_TX(mbB + 0, BBUF);
        bulk_cp(sB, (const char*)g_bsw, BBUF, mbB + 0);
    }

    float acc[2][2][2][4];
#pragma unroll
    for (int a = 0; a < 2; a++)
#pragma unroll
        for (int b = 0; b < 2; b++)
#pragma unroll
            for (int c = 0; c < 2; c++)
#pragma unroll
                for (int d = 0; d < 4; d++) acc[a][b][c][d] = 0.0f;

    float b1[4], b2[4];
    int   i1[4];
#pragma unroll
    for (int s = 0; s < 4; s++) { b1[s] = -3.0e38f; b2[s] = -3.0e38f; i1[s] = 0; }

    // A-fragment base addresses (per mm)
    uint32_t aAddr[2];
#pragma unroll
    for (int mm = 0; mm < 2; mm++) {
        int r = wm * 32 + mm * 16 + (lane & 15);
        aAddr[mm] = sA + r * AROWB + (r & 7) * 16;   // XOR g in later
    }
    // B-fragment row component (per kk-local): computed inline.
    const int krow_base = (lane & 7) + ((lane & 16) ? 8 : 0);

    MBARRIER_WAIT_PARITY(mbA, 0);

    for (int it = 0; it < NTILE; ++it) {
        const int slot = it & 1;
        __syncthreads();                       // all warps done with tile it-1
        if (tid == 0 && it + 1 < NTILE) {
            MBARRIER_EXPECT_TX(mbB + (slot ^ 1) * 8, BBUF);
            bulk_cp(sB + (slot ^ 1) * BBUF,
                    (const char*)g_bsw + (size_t)(it + 1) * BBUF,
                    BBUF, mbB + (slot ^ 1) * 8);
        }
        MBARRIER_WAIT_PARITY(mbB + slot * 8, (it >> 1) & 1);

        const uint32_t bbuf = sB + slot * BBUF;

        uint32_t af[2][2][4], bf[2][2][4];
        // preload kk = 0
#pragma unroll
        for (int mm = 0; mm < 2; mm++) {
            int r = wm * 32 + mm * 16 + (lane & 15);
            int g = 0 * 2 + (lane >> 4);
            ldsm4(af[0][mm], sA + r * AROWB + ((g ^ (r & 7)) * 16));
        }
#pragma unroll
        for (int nn2 = 0; nn2 < 2; nn2++) {
            int krow = krow_base;              // kk=0: kc=0, kkl=0
            int g = wn * 4 + nn2 * 2 + ((lane >> 3) & 1);
            ldsm4t(bf[0][nn2], bbuf + krow * 128 + ((g ^ (krow & 7)) * 16));
        }

#pragma unroll
        for (int kk = 0; kk < KSTEPS; kk++) {
            const int cur = kk & 1, nxt = cur ^ 1;
            if (kk + 1 < KSTEPS) {
                const int k2 = kk + 1;
#pragma unroll
                for (int mm = 0; mm < 2; mm++) {
                    int r = wm * 32 + mm * 16 + (lane & 15);
                    int g = k2 * 2 + (lane >> 4);
                    ldsm4(af[nxt][mm], sA + r * AROWB + ((g ^ (r & 7)) * 16));
                }
                const int kc2 = k2 >> 2, kl2 = k2 & 3;
#pragma unroll
                for (int nn2 = 0; nn2 < 2; nn2++) {
                    int krow = kl2 * 16 + krow_base;
                    int g = wn * 4 + nn2 * 2 + ((lane >> 3) & 1);
                    ldsm4t(bf[nxt][nn2],
                           bbuf + kc2 * 8192 + krow * 128 + ((g ^ (krow & 7)) * 16));
                }
            }
#pragma unroll
            for (int nn2 = 0; nn2 < 2; nn2++) {
#pragma unroll
                for (int mm = 0; mm < 2; mm++) {
                    mma16816(acc[mm][nn2][0], af[cur][mm], bf[cur][nn2][0], bf[cur][nn2][2]);
                    mma16816(acc[mm][nn2][1], af[cur][mm], bf[cur][nn2][1], bf[cur][nn2][3]);
                }
            }
        }

        // ---- fold accumulators into running top-2 ----
        const int colb = it * BN + wn * 32 + 2 * (lane & 3);
#pragma unroll
        for (int s = 0; s < 4; s++) {
            const int mm = s >> 1, h = s & 1;
#pragma unroll
            for (int nn2 = 0; nn2 < 2; nn2++) {
#pragma unroll
                for (int hn = 0; hn < 2; hn++) {
                    int cb = colb + nn2 * 16 + hn * 8;
                    float v0 = acc[mm][nn2][hn][h * 2];
                    if (v0 > b1[s]) { b2[s] = b1[s]; b1[s] = v0; i1[s] = cb; }
                    else if (v0 > b2[s]) b2[s] = v0;
                    float v1 = acc[mm][nn2][hn][h * 2 + 1];
                    if (v1 > b1[s]) { b2[s] = b1[s]; b1[s] = v1; i1[s] = cb + 1; }
                    else if (v1 > b2[s]) b2[s] = v1;
                    acc[mm][nn2][hn][h * 2] = 0.0f;
                    acc[mm][nn2][hn][h * 2 + 1] = 0.0f;
                }
            }
        }
    }

    // ---- quad-lane merge ----
#pragma unroll
    for (int s = 0; s < 4; s++) {
#pragma unroll
        for (int ofs = 1; ofs <= 2; ofs <<= 1) {
            float w1 = __shfl_xor_sync(0xFFFFFFFFu, b1[s], ofs);
            float w2 = __shfl_xor_sync(0xFFFFFFFFu, b2[s], ofs);
            int   k1 = __shfl_xor_sync(0xFFFFFFFFu, i1[s], ofs);
            if (w1 > b1[s] || (w1 == b1[s] && k1 < i1[s])) {
                b2[s] = fmaxf(b1[s], w2); b1[s] = w1; i1[s] = k1;
            } else {
                b2[s] = fmaxf(b2[s], w1);
            }
        }
    }

    // ---- cross-warp reduction via smem (reuse B buffers) ----
    __syncthreads();
    float* rv1 = (float*)(smem + ASMEM);
    float* rv2 = rv1 + BM * 2;
    int*   ri1 = (int*)(rv2 + BM * 2);
    if ((lane & 3) == 0) {
#pragma unroll
        for (int s = 0; s < 4; s++) {
            int row = wm * 32 + (s >> 1) * 16 + (s & 1) * 8 + (lane >> 2);
            rv1[row * 2 + wn] = b1[s];
            rv2[row * 2 + wn] = b2[s];
            ri1[row * 2 + wn] = i1[s];
        }
    }
    __syncthreads();
    if (tid < BM) {
        float v1 = rv1[tid * 2], v2 = rv2[tid * 2];
        int   j1 = ri1[tid * 2];
        float w1 = rv1[tid * 2 + 1], w2 = rv2[tid * 2 + 1];
        int   k1 = ri1[tid * 2 + 1];
        if (w1 > v1 || (w1 == v1 && k1 < j1)) { v2 = fmaxf(v1, w2); v1 = w1; j1 = k1; }
        else v2 = fmaxf(v2, w1);
        int row = m0 + tid;
        g_indices[row] = j1;
        outI[row] = (float)j1;
        if (v1 - v2 < DELTA) {
            int s = atomicAdd(&g_nflag, 1);
            g_flagged[s] = row;
        }
    }
}

// ===========================================================================
// 3a) Tiled batch rescore, bank-conflict-free (unchanged).
// ===========================================================================
__global__ __launch_bounds__(256) void rescore_part_kernel(const float* __restrict__ cb) {
    __shared__ float4 sp[48][20];
    __shared__ float  rv[16][16];
    __shared__ int    ri[16][16];
    const int nf = g_nflag;
    if (nf == 0) return;
    const int ngroups = (nf + 15) >> 4;
    const int nitems = ngroups * 4;
    const int tid = threadIdx.x;
    const int r = tid & 15;
    const int cl = tid >> 4;

    for (int item = blockIdx.x; item < nitems; item += gridDim.x) {
        const int g = item >> 2;
        const int s = item & 3;
        __syncthreads();
        for (int i = tid; i < 16 * 48; i += 256) {
            int rr = i / 48, qq = i % 48;
            int f = g * 16 + rr;
            int m = g_flagged[(f < nf) ? f : (nf - 1)];
            sp[qq][rr] = ((const float4*)(g_patches + (size_t)m * PD))[qq];
        }
        __syncthreads();

        float bv = -3.0e38f;
        int bi = 0;
        const int kbase = s * 1024 + cl * 64;
        for (int j = 0; j < 64; j++) {
            const int k = kbase + j;
            const float4* crow = (const float4*)(cb + (size_t)k * PD);
            float acc = 0.0f;
#pragma unroll 12
            for (int q = 0; q < 48; q++) {
                float4 c4 = crow[q];
                float4 p4 = sp[q][r];
                acc = fmaf(p4.x, c4.x, acc);
                acc = fmaf(p4.y, c4.y, acc);
                acc = fmaf(p4.z, c4.z, acc);
                acc = fmaf(p4.w, c4.w, acc);
            }
            if (acc > bv) { bv = acc; bi = k; }
        }
        rv[r][cl] = bv;
        ri[r][cl] = bi;
        __syncthreads();
        if (tid < 16) {
            float v = rv[tid][0];
            int ix = ri[tid][0];
#pragma unroll
            for (int t = 1; t < 16; t++) {
                float w = rv[tid][t];
                int k1 = ri[tid][t];
                if (w > v || (w == v && k1 < ix)) { v = w; ix = k1; }
            }
            int f = g * 16 + tid;
            if (f < nf) {
                g_part_val[(size_t)f * 4 + s] = v;
                g_part_idx[(size_t)f * 4 + s] = ix;
            }
        }
    }
}

__global__ void rescore_combine_kernel(float* __restrict__ outI) {
    int f = blockIdx.x * blockDim.x + threadIdx.x;
    if (f >= g_nflag) return;
    float bv = g_part_val[(size_t)f * 4];
    int bi = g_part_idx[(size_t)f * 4];
#pragma unroll
    for (int s = 1; s < 4; s++) {
        float v = g_part_val[(size_t)f * 4 + s];
        int ix = g_part_idx[(size_t)f * 4 + s];
        if (v > bv || (v == bv && ix < bi)) { bv = v; bi = ix; }
    }
    int m = g_flagged[f];
    g_indices[m] = bi;
    outI[m] = (float)bi;
}

// ===========================================================================
// 4) Fused tail: embed means (y=0,1) + VSA (y=2).
// ===========================================================================
__global__ __launch_bounds__(256) void tail_kernel(
    const float* __restrict__ emb, const float* __restrict__ cbv,
    const float* __restrict__ roles,
    float* __restrict__ outR, float* __restrict__ outL, float* __restrict__ outV)
{
    const int b = blockIdx.x;
    if (blockIdx.y < 2) {
        __shared__ int sIdx[NP];
        if (threadIdx.x < NP) sIdx[threadIdx.x] = g_indices[b * NP + threadIdx.x];
        __syncthreads();
        const int e4 = blockIdx.y * 256 + threadIdx.x;
        const float4* emb4 = (const float4*)emb;
        float4 s = make_float4(0.f, 0.f, 0.f, 0.f);
        float4 sl = make_float4(0.f, 0.f, 0.f, 0.f);
#pragma unroll 8
        for (int p = 0; p < NP; p++) {
            float4 v = emb4[(size_t)sIdx[p] * (ED / 4) + e4];
            s.x += v.x; s.y += v.y; s.z += v.z; s.w += v.w;
            int r = p >> 3, c = p & 7;
            if (r >= 3 && r < 6 && c >= 3 && c < 6) {
                sl.x += v.x; sl.y += v.y; sl.z += v.z; sl.w += v.w;
            }
        }
        const float iR = 1.0f / 64.0f, iL = 1.0f / 9.0f;
        ((float4*)outR)[(size_t)b * (ED / 4) + e4] =
            make_float4(s.x * iR, s.y * iR, s.z * iR, s.w * iR);
        ((float4*)outL)[(size_t)b * (ED / 4) + e4] =
            make_float4(sl.x * iL, sl.y * iL, sl.z * iL, sl.w * iL);
    } else {
        __shared__ int vIdx[16];
        __shared__ int vPos[16];
        if (threadIdx.x < 16) {
            int r = 2 + (threadIdx.x >> 2);
            int c = 2 + (threadIdx.x & 3);
            int p = r * 8 + c;
            vPos[threadIdx.x] = p;
            vIdx[threadIdx.x] = g_indices[b * NP + p];
        }
        __syncthreads();
        const float4* cbv4 = (const float4*)cbv;
        const float4* rol4 = (const float4*)roles;
#pragma unroll
        for (int half = 0; half < 2; half++) {
            const int v4 = half * 256 + threadIdx.x;
            int cx = 0, cy = 0, cz = 0, cw = 0;
#pragma unroll
            for (int t = 0; t < 16; t++) {
                float4 a = cbv4[(size_t)vIdx[t] * (VD / 4) + v4];
                float4 q = rol4[(size_t)vPos[t] * (VD / 4) + v4];
                cx += (a.x != q.x); cy += (a.y != q.y);
                cz += (a.z != q.z); cw += (a.w != q.w);
            }
            ((float4*)outV)[(size_t)b * (VD / 4) + v4] =
                make_float4(cx > 8 ? 1.f : 0.f, cy > 8 ? 1.f : 0.f,
                            cz > 8 ? 1.f : 0.f, cw > 8 ? 1.f : 0.f);
        }
    }
}

// ===========================================================================
extern "C" void kernel_launch(void* const* d_in, const int* in_sizes, int n_in,
                              void* d_out, int out_size)
{
    const float* pixels     = (const float*)d_in[0];
    const float* codebook   = (const float*)d_in[1];
    const float* embeddings = (const float*)d_in[2];
    const float* cbv        = (const float*)d_in[3];
    const float* roles      = (const float*)d_in[4];

    float* out  = (float*)d_out;
    float* outR = out;
    float* outV = out + (size_t)BATCH * ED;
    float* outI = out + 2 * (size_t)BATCH * ED;
    float* outL = out + 2 * (size_t)BATCH * ED + (size_t)BATCH * NP;

    static bool attr_set = false;
    if (!attr_set) {
        cudaFuncSetAttribute(gemm_mma_kernel,
                             cudaFuncAttributeMaxDynamicSharedMemorySize, GEMM_SMEM);
        attr_set = true;
    }

    prep_kernel<<<PFY_BLOCKS + CB_BLOCKS + 1, 256>>>(pixels, codebook);
    gemm_mma_kernel<<<MROWS / BM, GEMM_THREADS, GEMM_SMEM>>>(outI);
    rescore_part_kernel<<<1024, 256>>>(codebook);
    rescore_combine_kernel<<<MROWS / 256, 256>>>(outI);
    tail_kernel<<<dim3(BATCH, 3), 256>>>(embeddings, cbv, roles, outR, outL, outV);
}

// round 11
// speedup vs baseline: 6.3010x; 1.0535x over previous
#include <cuda_runtime.h>
#include <cuda_fp16.h>
#include <cstdint>

// ===========================================================================
// VQPatchEncoder — single-term fp16 mma.sync GEMM + DELTA-certified exact
// argmax. R11: patchify fused into GEMM prologue (A tile built in smem
// straight from pixels); rescore recomputes flagged patches from pixels.
// g_a / g_patches scratch eliminated. GEMM mainloop identical to R10.
// ===========================================================================

#define BATCH 1024
#define NP    64
#define PD    192
#define KC    4096
#define ED    2048
#define VD    2048
#define MROWS (BATCH * NP)      // 65536
#define BM    128
#define BN    64
#define NTILE  (KC / BN)         // 64
#define KSTEPS (PD / 16)         // 12
#define AROWB  (PD * 2)          // 384
#define ASMEM  (BM * AROWB)      // 49152
#define BBUF   (PD * BN * 2)     // 24576 (full-K tile)
#define NBUF   2
#define MBAR_OFF (ASMEM + NBUF * BBUF)        // 98304
#define GEMM_SMEM (MBAR_OFF + 32)             // 98336
#define GEMM_THREADS 256
#define DELTA 4e-3f

// ---- device-global scratch ------------------------------------------------
__device__ __align__(16) __half g_bsw[(size_t)PD * KC];   // per-tile smem images
__device__ int    g_indices[MROWS];
__device__ int    g_flagged[MROWS];
__device__ int    g_nflag;
__device__ float  g_part_val[(size_t)MROWS * 4];
__device__ int    g_part_idx[(size_t)MROWS * 4];

__device__ __forceinline__ uint32_t smem_u32(const void* p) {
    uint32_t a;
    asm("{ .reg .u64 t; cvta.to.shared.u64 t, %1; cvt.u32.u64 %0, t; }"
        : "=r"(a) : "l"(p));
    return a;
}

#define MBARRIER_INIT(mbar, cnt) \
    asm volatile("mbarrier.init.shared.b64 [%0], %1;" \
                 :: "r"((uint32_t)(mbar)), "r"((uint32_t)(cnt)) : "memory")
#define MBARRIER_EXPECT_TX(mbar, bytes) \
    asm volatile("mbarrier.arrive.expect_tx.shared.b64 _, [%0], %1;" \
                 :: "r"((uint32_t)(mbar)), "r"((uint32_t)(bytes)) : "memory")

#define MBARRIER_WAIT_PARITY(mbar_addr, phase_parity) do {                        \
    uint32_t _mbar = (uint32_t)(mbar_addr);                                       \
    uint32_t _par  = (uint32_t)(phase_parity);                                    \
    uint32_t _done;                                                               \
    asm volatile("{\n\t.reg .pred p;\n\t"                                         \
        "mbarrier.try_wait.parity.acquire.cta.shared::cta.b64 p, [%1], %2;\n\t"   \
        "selp.b32 %0, 1, 0, p;\n\t}"                                              \
        : "=r"(_done) : "r"(_mbar), "r"(_par) : "memory");                        \
    if (!_done) {                                                                 \
        asm volatile("{\n\t.reg .pred P1;\n\t"                                    \
            "WAIT_LOOP_%=:\n\t"                                                   \
            "mbarrier.try_wait.parity.acquire.cta.shared::cta.b64 P1, [%0], %1, 0x989680;\n\t" \
            "@P1 bra.uni WAIT_DONE_%=;\n\t"                                       \
            "bra.uni WAIT_LOOP_%=;\n\t"                                           \
            "WAIT_DONE_%=:\n\t}"                                                  \
            :: "r"(_mbar), "r"(_par) : "memory");                                 \
    }                                                                             \
} while (0)

__device__ __forceinline__ void bulk_cp(uint32_t dst, const void* src,
                                        uint32_t bytes, uint32_t mbar) {
    asm volatile(
        "cp.async.bulk.shared::cta.global.mbarrier::complete_tx::bytes "
        "[%0], [%1], %2, [%3];"
        :: "r"(dst), "l"(src), "r"(bytes), "r"(mbar) : "memory");
}

__device__ __forceinline__ void ldsm4(uint32_t* r, uint32_t addr) {
    asm volatile("ldmatrix.sync.aligned.m8n8.x4.shared.b16 {%0,%1,%2,%3}, [%4];"
                 : "=r"(r[0]), "=r"(r[1]), "=r"(r[2]), "=r"(r[3]) : "r"(addr));
}
__device__ __forceinline__ void ldsm4t(uint32_t* r, uint32_t addr) {
    asm volatile("ldmatrix.sync.aligned.m8n8.x4.trans.shared.b16 {%0,%1,%2,%3}, [%4];"
                 : "=r"(r[0]), "=r"(r[1]), "=r"(r[2]), "=r"(r[3]) : "r"(addr));
}
__device__ __forceinline__ void mma16816(float* c, const uint32_t* a,
                                         uint32_t b0, uint32_t b1) {
    asm volatile(
        "mma.sync.aligned.m16n8k16.row.col.f32.f16.f16.f32 "
        "{%0,%1,%2,%3}, {%4,%5,%6,%7}, {%8,%9}, {%0,%1,%2,%3};"
        : "+f"(c[0]), "+f"(c[1]), "+f"(c[2]), "+f"(c[3])
        : "r"(a[0]), "r"(a[1]), "r"(a[2]), "r"(a[3]), "r"(b0), "r"(b1));
}

// ===========================================================================
// 1) Prep: codebook smem-image layout + flag reset only.
// ===========================================================================
#define CB_BLOCKS  ((PD * KC) / 256)             // 3072
__global__ void prep_kernel(const float* __restrict__ cbk) {
    int bid = blockIdx.x;
    if (bid < CB_BLOCKS) {
        int idx = bid * 256 + threadIdx.x;
        int n = idx % KC;
        int d = idx / KC;
        int t = n >> 6, nt = n & 63;
        int kc = d >> 6, r = d & 63;
        int g = nt >> 3;
        size_t half_off = (size_t)(t * 3 + kc) * 4096
                        + r * 64 + ((g ^ (r & 7)) * 8) + (nt & 7);
        g_bsw[half_off] = __float2half_rn(cbk[(size_t)n * PD + d]);
    } else {
        if (threadIdx.x == 0) g_nflag = 0;
    }
}

// ===========================================================================
// 2) fp16 mma.sync GEMM + fused top-2 argmax. A tile built in the prologue
//    straight from pixels (patchify fused). Mainloop identical to R10.
// ===========================================================================
__global__ __launch_bounds__(GEMM_THREADS, 2) void gemm_mma_kernel(
    const float* __restrict__ pixels, float* __restrict__ outI)
{
    extern __shared__ char smem[];
    const uint32_t sA = smem_u32(smem);
    const uint32_t sB = sA + ASMEM;
    const uint32_t mbB = sA + MBAR_OFF;       // 2 barriers, 8B each
    const int tid = threadIdx.x;
    const int wid = tid >> 5;
    const int lane = tid & 31;
    const int wm = wid >> 1;    // 0..3 (32 M rows)
    const int wn = wid & 1;     // 0..1 (32 N cols)
    const int m0 = blockIdx.x * BM;

    // ---- init barriers + kick off B tile 0 (overlaps A build) ----
    if (tid == 0) {
        MBARRIER_INIT(mbB + 0, 1);
        MBARRIER_INIT(mbB + 8, 1);
        MBARRIER_EXPECT_TX(mbB + 0, BBUF);
        bulk_cp(sB, (const char*)g_bsw, BBUF, mbB + 0);
    }

    // ---- build A tile in smem from pixels (fused patchify) ----
    {
        const int m = tid >> 1;            // 0..127 patch within tile
        const int half = tid & 1;          // 0..1 (12 granules each)
        const int mg = m0 + m;
        const int b = mg >> 6, p = mg & 63;
        const int r = p >> 3, c = p & 7;
        const float* pix = pixels + (size_t)b * 3 * 4096 + c * 8;
#pragma unroll
        for (int gi = 0; gi < 12; gi++) {
            int g = half * 12 + gi;
            int d0 = g * 8;
            int ch = d0 >> 6;
            int pr = (d0 & 63) >> 3;
            const float4* src = (const float4*)(pix + (size_t)ch * 4096 + (r * 8 + pr) * 64);
            float4 v0 = src[0], v1 = src[1];
            __half2 h0 = __floats2half2_rn(v0.x, v0.y);
            __half2 h1 = __floats2half2_rn(v0.z, v0.w);
            __half2 h2 = __floats2half2_rn(v1.x, v1.y);
            __half2 h3 = __floats2half2_rn(v1.z, v1.w);
            uint4 u;
            u.x = *(uint32_t*)&h0; u.y = *(uint32_t*)&h1;
            u.z = *(uint32_t*)&h2; u.w = *(uint32_t*)&h3;
            *(uint4*)(smem + m * AROWB + ((g ^ (m & 7)) * 16)) = u;
        }
    }
    __syncthreads();   // A ready + barrier init visible to all threads

    float acc[2][2][2][4];
#pragma unroll
    for (int a = 0; a < 2; a++)
#pragma unroll
        for (int b = 0; b < 2; b++)
#pragma unroll
            for (int c = 0; c < 2; c++)
#pragma unroll
                for (int d = 0; d < 4; d++) acc[a][b][c][d] = 0.0f;

    float b1[4], b2[4];
    int   i1[4];
#pragma unroll
    for (int s = 0; s < 4; s++) { b1[s] = -3.0e38f; b2[s] = -3.0e38f; i1[s] = 0; }

    const int krow_base = (lane & 7) + ((lane & 16) ? 8 : 0);

    for (int it = 0; it < NTILE; ++it) {
        const int slot = it & 1;
        if (it) __syncthreads();               // all warps done with tile it-1
        if (tid == 0 && it + 1 < NTILE) {
            MBARRIER_EXPECT_TX(mbB + (slot ^ 1) * 8, BBUF);
            bulk_cp(sB + (slot ^ 1) * BBUF,
                    (const char*)g_bsw + (size_t)(it + 1) * BBUF,
                    BBUF, mbB + (slot ^ 1) * 8);
        }
        MBARRIER_WAIT_PARITY(mbB + slot * 8, (it >> 1) & 1);

        const uint32_t bbuf = sB + slot * BBUF;

        uint32_t af[2][2][4], bf[2][2][4];
        // preload kk = 0
#pragma unroll
        for (int mm = 0; mm < 2; mm++) {
            int r = wm * 32 + mm * 16 + (lane & 15);
            int g = (lane >> 4);
            ldsm4(af[0][mm], sA + r * AROWB + ((g ^ (r & 7)) * 16));
        }
#pragma unroll
        for (int nn2 = 0; nn2 < 2; nn2++) {
            int krow = krow_base;
            int g = wn * 4 + nn2 * 2 + ((lane >> 3) & 1);
            ldsm4t(bf[0][nn2], bbuf + krow * 128 + ((g ^ (krow & 7)) * 16));
        }

#pragma unroll
        for (int kk = 0; kk < KSTEPS; kk++) {
            const int cur = kk & 1, nxt = cur ^ 1;
            if (kk + 1 < KSTEPS) {
                const int k2 = kk + 1;
#pragma unroll
                for (int mm = 0; mm < 2; mm++) {
                    int r = wm * 32 + mm * 16 + (lane & 15);
                    int g = k2 * 2 + (lane >> 4);
                    ldsm4(af[nxt][mm], sA + r * AROWB + ((g ^ (r & 7)) * 16));
                }
                const int kc2 = k2 >> 2, kl2 = k2 & 3;
#pragma unroll
                for (int nn2 = 0; nn2 < 2; nn2++) {
                    int krow = kl2 * 16 + krow_base;
                    int g = wn * 4 + nn2 * 2 + ((lane >> 3) & 1);
                    ldsm4t(bf[nxt][nn2],
                           bbuf + kc2 * 8192 + krow * 128 + ((g ^ (krow & 7)) * 16));
                }
            }
#pragma unroll
            for (int nn2 = 0; nn2 < 2; nn2++) {
#pragma unroll
                for (int mm = 0; mm < 2; mm++) {
                    mma16816(acc[mm][nn2][0], af[cur][mm], bf[cur][nn2][0], bf[cur][nn2][2]);
                    mma16816(acc[mm][nn2][1], af[cur][mm], bf[cur][nn2][1], bf[cur][nn2][3]);
                }
            }
        }

        // ---- fold accumulators into running top-2 ----
        const int colb = it * BN + wn * 32 + 2 * (lane & 3);
#pragma unroll
        for (int s = 0; s < 4; s++) {
            const int mm = s >> 1, h = s & 1;
#pragma unroll
            for (int nn2 = 0; nn2 < 2; nn2++) {
#pragma unroll
                for (int hn = 0; hn < 2; hn++) {
                    int cb = colb + nn2 * 16 + hn * 8;
                    float v0 = acc[mm][nn2][hn][h * 2];
                    if (v0 > b1[s]) { b2[s] = b1[s]; b1[s] = v0; i1[s] = cb; }
                    else if (v0 > b2[s]) b2[s] = v0;
                    float v1 = acc[mm][nn2][hn][h * 2 + 1];
                    if (v1 > b1[s]) { b2[s] = b1[s]; b1[s] = v1; i1[s] = cb + 1; }
                    else if (v1 > b2[s]) b2[s] = v1;
                    acc[mm][nn2][hn][h * 2] = 0.0f;
                    acc[mm][nn2][hn][h * 2 + 1] = 0.0f;
                }
            }
        }
    }

    // ---- quad-lane merge ----
#pragma unroll
    for (int s = 0; s < 4; s++) {
#pragma unroll
        for (int ofs = 1; ofs <= 2; ofs <<= 1) {
            float w1 = __shfl_xor_sync(0xFFFFFFFFu, b1[s], ofs);
            float w2 = __shfl_xor_sync(0xFFFFFFFFu, b2[s], ofs);
            int   k1 = __shfl_xor_sync(0xFFFFFFFFu, i1[s], ofs);
            if (w1 > b1[s] || (w1 == b1[s] && k1 < i1[s])) {
                b2[s] = fmaxf(b1[s], w2); b1[s] = w1; i1[s] = k1;
            } else {
                b2[s] = fmaxf(b2[s], w1);
            }
        }
    }

    // ---- cross-warp reduction via smem (reuse B buffers) ----
    __syncthreads();
    float* rv1 = (float*)(smem + ASMEM);
    float* rv2 = rv1 + BM * 2;
    int*   ri1 = (int*)(rv2 + BM * 2);
    if ((lane & 3) == 0) {
#pragma unroll
        for (int s = 0; s < 4; s++) {
            int row = wm * 32 + (s >> 1) * 16 + (s & 1) * 8 + (lane >> 2);
            rv1[row * 2 + wn] = b1[s];
            rv2[row * 2 + wn] = b2[s];
            ri1[row * 2 + wn] = i1[s];
        }
    }
    __syncthreads();
    if (tid < BM) {
        float v1 = rv1[tid * 2], v2 = rv2[tid * 2];
        int   j1 = ri1[tid * 2];
        float w1 = rv1[tid * 2 + 1], w2 = rv2[tid * 2 + 1];
        int   k1 = ri1[tid * 2 + 1];
        if (w1 > v1 || (w1 == v1 && k1 < j1)) { v2 = fmaxf(v1, w2); v1 = w1; j1 = k1; }
        else v2 = fmaxf(v2, w1);
        int row = m0 + tid;
        g_indices[row] = j1;
        outI[row] = (float)j1;
        if (v1 - v2 < DELTA) {
            int s = atomicAdd(&g_nflag, 1);
            g_flagged[s] = row;
        }
    }
}

// ===========================================================================
// 3a) Tiled batch rescore, bank-conflict-free. Flagged patch rows are
//     recomputed from pixels (patchify is a pure copy -> identical fp32 bits).
// ===========================================================================
__global__ __launch_bounds__(256) void rescore_part_kernel(
    const float* __restrict__ pixels, const float* __restrict__ cb)
{
    __shared__ float4 sp[48][20];
    __shared__ float  rv[16][16];
    __shared__ int    ri[16][16];
    const int nf = g_nflag;
    if (nf == 0) return;
    const int ngroups = (nf + 15) >> 4;
    const int nitems = ngroups * 4;
    const int tid = threadIdx.x;
    const int r = tid & 15;
    const int cl = tid >> 4;
    const float4* pix4 = (const float4*)pixels;

    for (int item = blockIdx.x; item < nitems; item += gridDim.x) {
        const int g = item >> 2;
        const int s = item & 3;
        __syncthreads();
        for (int i = tid; i < 16 * 48; i += 256) {
            int rr = i / 48, qq = i % 48;
            int f = g * 16 + rr;
            int m = g_flagged[(f < nf) ? f : (nf - 1)];
            int b = m >> 6, p = m & 63;
            int pr_ = (p >> 3), pc_ = (p & 7);
            int d0 = qq * 4;
            int ch = d0 >> 6, rem = d0 & 63;
            int prr = rem >> 3, pcc = rem & 7;
            sp[qq][rr] = pix4[((size_t)(b * 3 + ch) * 64 + pr_ * 8 + prr) * 16
                              + pc_ * 2 + (pcc >> 2)];
        }
        __syncthreads();

        float bv = -3.0e38f;
        int bi = 0;
        const int kbase = s * 1024 + cl * 64;
        for (int j = 0; j < 64; j++) {
            const int k = kbase + j;
            const float4* crow = (const float4*)(cb + (size_t)k * PD);
            float acc = 0.0f;
#pragma unroll 12
            for (int q = 0; q < 48; q++) {
                float4 c4 = crow[q];
                float4 p4 = sp[q][r];
                acc = fmaf(p4.x, c4.x, acc);
                acc = fmaf(p4.y, c4.y, acc);
                acc = fmaf(p4.z, c4.z, acc);
                acc = fmaf(p4.w, c4.w, acc);
            }
            if (acc > bv) { bv = acc; bi = k; }
        }
        rv[r][cl] = bv;
        ri[r][cl] = bi;
        __syncthreads();
        if (tid < 16) {
            float v = rv[tid][0];
            int ix = ri[tid][0];
#pragma unroll
            for (int t = 1; t < 16; t++) {
                float w = rv[tid][t];
                int k1 = ri[tid][t];
                if (w > v || (w == v && k1 < ix)) { v = w; ix = k1; }
            }
            int f = g * 16 + tid;
            if (f < nf) {
                g_part_val[(size_t)f * 4 + s] = v;
                g_part_idx[(size_t)f * 4 + s] = ix;
            }
        }
    }
}

__global__ void rescore_combine_kernel(float* __restrict__ outI) {
    int f = blockIdx.x * blockDim.x + threadIdx.x;
    if (f >= g_nflag) return;
    float bv = g_part_val[(size_t)f * 4];
    int bi = g_part_idx[(size_t)f * 4];
#pragma unroll
    for (int s = 1; s < 4; s++) {
        float v = g_part_val[(size_t)f * 4 + s];
        int ix = g_part_idx[(size_t)f * 4 + s];
        if (v > bv || (v == bv && ix < bi)) { bv = v; bi = ix; }
    }
    int m = g_flagged[f];
    g_indices[m] = bi;
    outI[m] = (float)bi;
}

// ===========================================================================
// 4) Fused tail: embed means (y=0,1) + VSA (y=2).
// ===========================================================================
__global__ __launch_bounds__(256) void tail_kernel(
    const float* __restrict__ emb, const float* __restrict__ cbv,
    const float* __restrict__ roles,
    float* __restrict__ outR, float* __restrict__ outL, float* __restrict__ outV)
{
    const int b = blockIdx.x;
    if (blockIdx.y < 2) {
        __shared__ int sIdx[NP];
        if (threadIdx.x < NP) sIdx[threadIdx.x] = g_indices[b * NP + threadIdx.x];
        __syncthreads();
        const int e4 = blockIdx.y * 256 + threadIdx.x;
        const float4* emb4 = (const float4*)emb;
        float4 s = make_float4(0.f, 0.f, 0.f, 0.f);
        float4 sl = make_float4(0.f, 0.f, 0.f, 0.f);
#pragma unroll 8
        for (int p = 0; p < NP; p++) {
            float4 v = emb4[(size_t)sIdx[p] * (ED / 4) + e4];
            s.x += v.x; s.y += v.y; s.z += v.z; s.w += v.w;
            int r = p >> 3, c = p & 7;
            if (r >= 3 && r < 6 && c >= 3 && c < 6) {
                sl.x += v.x; sl.y += v.y; sl.z += v.z; sl.w += v.w;
            }
        }
        const float iR = 1.0f / 64.0f, iL = 1.0f / 9.0f;
        ((float4*)outR)[(size_t)b * (ED / 4) + e4] =
            make_float4(s.x * iR, s.y * iR, s.z * iR, s.w * iR);
        ((float4*)outL)[(size_t)b * (ED / 4) + e4] =
            make_float4(sl.x * iL, sl.y * iL, sl.z * iL, sl.w * iL);
    } else {
        __shared__ int vIdx[16];
        __shared__ int vPos[16];
        if (threadIdx.x < 16) {
            int r = 2 + (threadIdx.x >> 2);
            int c = 2 + (threadIdx.x & 3);
            int p = r * 8 + c;
            vPos[threadIdx.x] = p;
            vIdx[threadIdx.x] = g_indices[b * NP + p];
        }
        __syncthreads();
        const float4* cbv4 = (const float4*)cbv;
        const float4* rol4 = (const float4*)roles;
#pragma unroll
        for (int half = 0; half < 2; half++) {
            const int v4 = half * 256 + threadIdx.x;
            int cx = 0, cy = 0, cz = 0, cw = 0;
#pragma unroll
            for (int t = 0; t < 16; t++) {
                float4 a = cbv4[(size_t)vIdx[t] * (VD / 4) + v4];
                float4 q = rol4[(size_t)vPos[t] * (VD / 4) + v4];
                cx += (a.x != q.x); cy += (a.y != q.y);
                cz += (a.z != q.z); cw += (a.w != q.w);
            }
            ((float4*)outV)[(size_t)b * (VD / 4) + v4] =
                make_float4(cx > 8 ? 1.f : 0.f, cy > 8 ? 1.f : 0.f,
                            cz > 8 ? 1.f : 0.f, cw > 8 ? 1.f : 0.f);
        }
    }
}

// ===========================================================================
extern "C" void kernel_launch(void* const* d_in, const int* in_sizes, int n_in,
                              void* d_out, int out_size)
{
    const float* pixels     = (const float*)d_in[0];
    const float* codebook   = (const float*)d_in[1];
    const float* embeddings = (const float*)d_in[2];
    const float* cbv        = (const float*)d_in[3];
    const float* roles      = (const float*)d_in[4];

    float* out  = (float*)d_out;
    float* outR = out;
    float* outV = out + (size_t)BATCH * ED;
    float* outI = out + 2 * (size_t)BATCH * ED;
    float* outL = out + 2 * (size_t)BATCH * ED + (size_t)BATCH * NP;

    static bool attr_set = false;
    if (!attr_set) {
        cudaFuncSetAttribute(gemm_mma_kernel,
                             cudaFuncAttributeMaxDynamicSharedMemorySize, GEMM_SMEM);
        attr_set = true;
    }

    prep_kernel<<<CB_BLOCKS + 1, 256>>>(codebook);
    gemm_mma_kernel<<<MROWS / BM, GEMM_THREADS, GEMM_SMEM>>>(pixels, outI);
    rescore_part_kernel<<<1024, 256>>>(pixels, codebook);
    rescore_combine_kernel<<<MROWS / 256, 256>>>(outI);
    tail_kernel<<<dim3(BATCH, 3), 256>>>(embeddings, cbv, roles, outR, outL, outV);
}